// round 9
// baseline (speedup 1.0000x reference)
#include <cuda_runtime.h>
#include <cuda_fp16.h>
#include <cstdint>

#define T2 2048
#define T1 2048
#define EE 512
#define FF 2048
#define NL 4
#define NH 8
#define LOG2E 1.4426950408889634f

// ---------------- scratch (device globals; allocation-free) ----------------
__device__ float g_h    [T2*EE];
__device__ float g_proj [T2*EE];
__device__ float g_proj2[T2*EE];
__device__ float g_ffn  [T2*FF];
__device__ float g_op   [2*T2*EE];      // split-KV partial O (unnormalized)
__device__ float g_ml   [2*NH*T2*2];    // split-KV per-row (m, l), m in log2 dom
__device__ float g_mlw  [2*NH*T2];      // combine weights w0', w1'
__device__ float g_zb   [FF];           // zero bias (zero-initialized)
// split-pair storage for attention operands
__device__ __half g_qh[T2*EE], g_ql[T2*EE];     // SA Q (pre-scaled by log2e)
__device__ __half g_kh[T2*EE], g_kl[T2*EE];
__device__ __half g_vh[T2*EE], g_vl[T2*EE];
__device__ __half g_hh[T2*EE], g_hl[T2*EE];     // CA Q = h (pre-scaled by log2e)
__device__ __half g_Ksh[T1*EE], g_Ksl[T1*EE];
__device__ __half g_Vsh[T1*EE], g_Vsl[T1*EE];

// ---------------- helpers ----------------
__device__ __forceinline__ void hmma(float* d, const uint32_t* a, const uint32_t* b) {
    asm volatile(
        "mma.sync.aligned.m16n8k16.row.col.f32.f16.f16.f32 "
        "{%0,%1,%2,%3}, {%4,%5,%6,%7}, {%8,%9}, {%0,%1,%2,%3};"
        : "+f"(d[0]), "+f"(d[1]), "+f"(d[2]), "+f"(d[3])
        : "r"(a[0]), "r"(a[1]), "r"(a[2]), "r"(a[3]), "r"(b[0]), "r"(b[1]));
}
#define LDSM4(R, PTR) do {                                                     \
    uint32_t a_ = (uint32_t)__cvta_generic_to_shared(PTR);                     \
    asm volatile("ldmatrix.sync.aligned.m8n8.x4.shared.b16 {%0,%1,%2,%3}, [%4];" \
        : "=r"((R)[0]), "=r"((R)[1]), "=r"((R)[2]), "=r"((R)[3]) : "r"(a_));   \
} while (0)
#define LDSM4T(R, PTR) do {                                                    \
    uint32_t a_ = (uint32_t)__cvta_generic_to_shared(PTR);                     \
    asm volatile("ldmatrix.sync.aligned.m8n8.x4.trans.shared.b16 {%0,%1,%2,%3}, [%4];" \
        : "=r"((R)[0]), "=r"((R)[1]), "=r"((R)[2]), "=r"((R)[3]) : "r"(a_));   \
} while (0)

__device__ __forceinline__ float ex2(float x) {
    float y;
    asm("ex2.approx.f32 %0, %1;" : "=f"(y) : "f"(x));
    return y;
}
__device__ __forceinline__ uint32_t packh2(float x, float y) {
    __half2 h = __floats2half2_rn(x, y);
    return *reinterpret_cast<uint32_t*>(&h);
}
// 2-term fp16 split: (x,y) -> hi pair + lo pair; x ≈ hi + lo to ~2.4e-7 rel.
__device__ __forceinline__ void split2(float x, float y, uint32_t& hi, uint32_t& lo) {
    float hx = __half2float(__float2half_rn(x));
    float hy = __half2float(__float2half_rn(y));
    hi = packh2(hx, hy);
    lo = packh2(x - hx, y - hy);
}

// ---------------- elementwise copy ----------------
__global__ void copyk(const float* __restrict__ in, float* __restrict__ out) {
    size_t i = ((size_t)blockIdx.x * blockDim.x + threadIdx.x) * 4;
    *(float4*)(out + i) = *(const float4*)(in + i);
}

// ---------------- ml -> combine weights (m in log2 domain) ----------------
__global__ __launch_bounds__(256) void mlw_kernel(
    const float* __restrict__ ml, float* __restrict__ mlw)
{
    const int i = blockIdx.x * 256 + threadIdx.x;   // i = head*T2 + row
    float m0 = ml[i * 2 + 0];
    float l0 = ml[i * 2 + 1];
    float m1 = ml[(NH * T2 + i) * 2 + 0];
    float l1 = ml[(NH * T2 + i) * 2 + 1];
    float m = fmaxf(m0, m1);
    float w0 = ex2(m0 - m), w1 = ex2(m1 - m);
    float inv = 1.f / (l0 * w0 + l1 * w1);
    mlw[i] = w0 * inv;
    mlw[NH * T2 + i] = w1 * inv;
}

// ---------------- GEMM output descriptor ----------------
struct GOut {
    const float* B;
    const float* bias;
    float* c32;          // fp32 output (or nullptr)
    __half* ch;          // split-pair hi output (or nullptr)
    __half* cl;          // split-pair lo output
    float scl;           // scale applied to pair output only
};

// ---------------- fp16-split GEMM: C = act(A @ B + bias), tile 128x64 -------
// 256 threads, 8 warps (4x2), warp 32x32, BK=32, 2-stage register pipeline.
// CMB=1: A is split-KV partial base (op); combine with mlw during load.
// stage halves: Ah[128][40]@0 Al@5120 Bh[32][72]@10240 Bl@12544; GST=14848.
#define GST 14848
#define GSMEM (2 * GST * 2)   // 59392 B

template<int CMB>
__global__ __launch_bounds__(256, 2) void gemm_mma(
    const float* __restrict__ A, const float* __restrict__ mlw,
    GOut o0, GOut o1, GOut o2,
    int N, int lda, int kCnt, int aoffZ, int act)
{
    extern __shared__ __half hsm[];
    const int z = blockIdx.z;
    const GOut o = (z == 0) ? o0 : ((z == 1) ? o1 : o2);
    const float* B = o.B;
    const float* Az = A + (size_t)z * aoffZ;

    const int tid = threadIdx.x;
    const int wid = tid >> 5, lane = tid & 31;
    const int g = lane >> 2, t = lane & 3;
    const int bm = blockIdx.y * 128, bn = blockIdx.x * 64;
    const int wm = (wid >> 1) * 32, wn = (wid & 1) * 32;

    float acc[2][4][4];
    #pragma unroll
    for (int mi = 0; mi < 2; mi++)
        #pragma unroll
        for (int nj = 0; nj < 4; nj++)
            #pragma unroll
            for (int r = 0; r < 4; r++) acc[mi][nj][r] = 0.f;

    const int NC = kCnt >> 5;
    float4 ra[4], rb[2];

    #define GLDG(c) do {                                                        \
        _Pragma("unroll")                                                       \
        for (int j_ = 0; j_ < 4; j_++) {                                        \
            int idx_ = tid + j_ * 256;                                          \
            int row_ = bm + (idx_ >> 3);                                        \
            int col_ = (c) * 32 + (idx_ & 7) * 4;                               \
            if (CMB) {                                                          \
                int head_ = (c) >> 1;                                           \
                float w0_ = mlw[head_ * T2 + row_];                             \
                float w1_ = mlw[NH * T2 + head_ * T2 + row_];                   \
                float4 a0_ = *(const float4*)(Az + (size_t)row_ * EE + col_);   \
                float4 a1_ = *(const float4*)(Az + (size_t)T2 * EE              \
                                              + (size_t)row_ * EE + col_);      \
                ra[j_].x = a0_.x * w0_ + a1_.x * w1_;                           \
                ra[j_].y = a0_.y * w0_ + a1_.y * w1_;                           \
                ra[j_].z = a0_.z * w0_ + a1_.z * w1_;                           \
                ra[j_].w = a0_.w * w0_ + a1_.w * w1_;                           \
            } else {                                                            \
                ra[j_] = *(const float4*)(Az + (size_t)row_ * lda + col_);      \
            }                                                                   \
        }                                                                       \
        _Pragma("unroll")                                                       \
        for (int j_ = 0; j_ < 2; j_++) {                                        \
            int idx_ = tid + j_ * 256;                                          \
            rb[j_] = *(const float4*)(B + (size_t)((c) * 32 + (idx_ >> 4)) * N  \
                                      + bn + (idx_ & 15) * 4);                  \
        }                                                                       \
    } while (0)

    #define GSTS(s) do {                                                        \
        __half* st_ = hsm + (s) * GST;                                          \
        _Pragma("unroll")                                                       \
        for (int j_ = 0; j_ < 4; j_++) {                                        \
            int idx_ = tid + j_ * 256;                                          \
            int m_ = idx_ >> 3, kq_ = idx_ & 7;                                 \
            uint32_t h01, l01, h23, l23;                                        \
            split2(ra[j_].x, ra[j_].y, h01, l01);                               \
            split2(ra[j_].z, ra[j_].w, h23, l23);                               \
            *(uint2*)(st_ + m_ * 40 + kq_ * 4) = make_uint2(h01, h23);          \
            *(uint2*)(st_ + 5120 + m_ * 40 + kq_ * 4) = make_uint2(l01, l23);   \
        }                                                                       \
        _Pragma("unroll")                                                       \
        for (int j_ = 0; j_ < 2; j_++) {                                        \
            int idx_ = tid + j_ * 256;                                          \
            int k_ = idx_ >> 4, nq_ = idx_ & 15;                                \
            uint32_t h01, l01, h23, l23;                                        \
            split2(rb[j_].x, rb[j_].y, h01, l01);                               \
            split2(rb[j_].z, rb[j_].w, h23, l23);                               \
            *(uint2*)(st_ + 10240 + k_ * 72 + nq_ * 4) = make_uint2(h01, h23);  \
            *(uint2*)(st_ + 12544 + k_ * 72 + nq_ * 4) = make_uint2(l01, l23);  \
        }                                                                       \
    } while (0)

    GLDG(0); GSTS(0);
    if (NC > 1) GLDG(1);
    __syncthreads();

    for (int c = 0; c < NC; c++) {
        if (c + 1 < NC) GSTS((c + 1) & 1);
        if (c + 2 < NC) GLDG(c + 2);

        __half* st = hsm + (c & 1) * GST;
        #pragma unroll
        for (int ks = 0; ks < 2; ks++) {
            const int kb = ks * 16;
            uint32_t Ahf[2][4], Alf[2][4], Bhf[2][4], Blf[2][4];
            const int arow = (lane & 15), acol = kb + (lane >> 4) * 8;
            #pragma unroll
            for (int mi = 0; mi < 2; mi++) {
                __half* ap = st + (wm + mi * 16 + arow) * 40 + acol;
                LDSM4(Ahf[mi], ap);
                LDSM4(Alf[mi], ap + 5120);
            }
            const int krow = kb + ((lane >> 3) & 1) * 8 + (lane & 7);
            #pragma unroll
            for (int nq = 0; nq < 2; nq++) {
                const int ncol = wn + nq * 16 + ((lane >> 4) & 1) * 8;
                __half* bp = st + 10240 + krow * 72 + ncol;
                LDSM4T(Bhf[nq], bp);
                LDSM4T(Blf[nq], bp + 2304);
            }
            #pragma unroll
            for (int mi = 0; mi < 2; mi++)
                #pragma unroll
                for (int nj = 0; nj < 4; nj++) {
                    const uint32_t* bh = &Bhf[nj >> 1][(nj & 1) * 2];
                    const uint32_t* bl = &Blf[nj >> 1][(nj & 1) * 2];
                    hmma(acc[mi][nj], Ahf[mi], bh);
                    hmma(acc[mi][nj], Ahf[mi], bl);
                    hmma(acc[mi][nj], Alf[mi], bh);
                }
        }
        __syncthreads();
    }

    #pragma unroll
    for (int mi = 0; mi < 2; mi++) {
        #pragma unroll
        for (int nj = 0; nj < 4; nj++) {
            const int row = bm + wm + mi * 16 + g;
            const int col = bn + wn + nj * 8 + t * 2;
            float2 bv = *(const float2*)(o.bias + col);
            float2 w0, w1;
            w0.x = acc[mi][nj][0] + bv.x; w0.y = acc[mi][nj][1] + bv.y;
            w1.x = acc[mi][nj][2] + bv.x; w1.y = acc[mi][nj][3] + bv.y;
            if (act) {
                w0.x = fmaxf(w0.x, 0.f); w0.y = fmaxf(w0.y, 0.f);
                w1.x = fmaxf(w1.x, 0.f); w1.y = fmaxf(w1.y, 0.f);
            }
            if (o.c32) {
                *(float2*)(o.c32 + (size_t)row * N + col) = w0;
                *(float2*)(o.c32 + (size_t)(row + 8) * N + col) = w1;
            }
            if (o.ch) {
                uint32_t hh_, ll_;
                split2(w0.x * o.scl, w0.y * o.scl, hh_, ll_);
                *(uint32_t*)(o.ch + (size_t)row * N + col) = hh_;
                *(uint32_t*)(o.cl + (size_t)row * N + col) = ll_;
                split2(w1.x * o.scl, w1.y * o.scl, hh_, ll_);
                *(uint32_t*)(o.ch + (size_t)(row + 8) * N + col) = hh_;
                *(uint32_t*)(o.cl + (size_t)(row + 8) * N + col) = ll_;
            }
        }
    }
    #undef GLDG
    #undef GSTS
}

// ---------------- fp16-pair flash attention, split-KV x2 --------------------
// Operands arrive as pre-split half pairs (Q pre-scaled by log2e).
// CTA: 128 q-rows x 1 head x 1 KV-half; 4 warps x 32 q-rows; KV chunks of 64.
// smem halves: Qh[128][72]@0 Ql@9216 Kh[64][72]@18432 Kl@23040 Vh@27648 Vl@32256
#define ASMEM 73728

__global__ __launch_bounds__(128, 2) void attn_mma(
    const __half* __restrict__ Qh_g, const __half* __restrict__ Ql_g,
    const __half* __restrict__ Kh_g, const __half* __restrict__ Kl_g,
    const __half* __restrict__ Vh_g, const __half* __restrict__ Vl_g,
    const float* __restrict__ mask,
    float* __restrict__ Opart, float* __restrict__ ml,
    int Tk, int maskFull)
{
    extern __shared__ __half hsm[];
    __half* Qh = hsm;              // lo at +9216
    __half* Kh = hsm + 18432;      // lo at +4608
    __half* Vh = hsm + 27648;      // lo at +4608

    const int tid = threadIdx.x;
    const int wid = tid >> 5, lane = tid & 31;
    const int g = lane >> 2, t = lane & 3;
    const int q0 = blockIdx.x * 128, hc = blockIdx.y * 64;
    const int s = blockIdx.z;
    const int kbase = s * (Tk >> 1);
    const int wm = wid * 32;
    float* op = Opart + (size_t)s * T2 * EE;

    // Q tile 128x64 pairs -> smem (pure copy)
    #pragma unroll
    for (int j = 0; j < 16; j++) {
        int idx = tid + j * 128;
        int r = idx >> 4, dq = idx & 15;
        size_t off = (size_t)(q0 + r) * EE + hc + dq * 4;
        *(uint2*)(Qh + r * 72 + dq * 4) = *(const uint2*)(Qh_g + off);
        *(uint2*)(Qh + 9216 + r * 72 + dq * 4) = *(const uint2*)(Ql_g + off);
    }

    // K/V staging registers (uint2 pairs; disjoint lifetimes)
    uint2 rkv[16];
    #pragma unroll
    for (int j = 0; j < 8; j++) {
        int idx = tid + j * 128;
        size_t off = (size_t)(kbase + (idx >> 4)) * EE + hc + (idx & 15) * 4;
        rkv[j]     = *(const uint2*)(Kh_g + off);
        rkv[j + 8] = *(const uint2*)(Kl_g + off);
    }

    float m_run[4], l_run[4];
    #pragma unroll
    for (int r = 0; r < 4; r++) { m_run[r] = -1e30f; l_run[r] = 0.f; }
    float oacc[2][8][4];
    #pragma unroll
    for (int mi = 0; mi < 2; mi++)
        #pragma unroll
        for (int nj = 0; nj < 8; nj++)
            #pragma unroll
            for (int r = 0; r < 4; r++) oacc[mi][nj][r] = 0.f;

    const int NCH = Tk >> 7;    // chunks of 64 within this half
    for (int c = 0; c < NCH; c++) {
        const int kr0 = kbase + c * 64;

        // ---- STS K pairs from rkv (pure copy) ----
        #pragma unroll
        for (int j = 0; j < 8; j++) {
            int idx = tid + j * 128;
            int kr = idx >> 4, dq = idx & 15;
            *(uint2*)(Kh + kr * 72 + dq * 4) = rkv[j];
            *(uint2*)(Kh + 4608 + kr * 72 + dq * 4) = rkv[j + 8];
        }
        __syncthreads();   // K (and Q on c=0) ready; all warps past PV(c-1)

        // ---- LDG V pairs chunk c (latency hidden by S-MMA) ----
        #pragma unroll
        for (int j = 0; j < 8; j++) {
            int idx = tid + j * 128;
            size_t off = (size_t)(kr0 + (idx >> 4)) * EE + hc + (idx & 15) * 4;
            rkv[j]     = *(const uint2*)(Vh_g + off);
            rkv[j + 8] = *(const uint2*)(Vl_g + off);
        }

        // ---- S = Q @ K^T (log2 domain: Q pre-scaled) ----
        float sreg[2][8][4];
        #pragma unroll
        for (int mi = 0; mi < 2; mi++)
            #pragma unroll
            for (int nj = 0; nj < 8; nj++)
                #pragma unroll
                for (int r = 0; r < 4; r++) sreg[mi][nj][r] = 0.f;

        #pragma unroll
        for (int ks = 0; ks < 4; ks++) {
            uint32_t qh[2][4], ql[2][4];
            #pragma unroll
            for (int mi = 0; mi < 2; mi++) {
                __half* qp = Qh + (wm + mi * 16 + (lane & 15)) * 72 + ks * 16 + (lane >> 4) * 8;
                LDSM4(qh[mi], qp);
                LDSM4(ql[mi], qp + 9216);
            }
            const int kvrow = ((lane >> 4) & 1) * 8 + (lane & 7);
            const int dcol = ks * 16 + ((lane >> 3) & 1) * 8;
            #pragma unroll
            for (int nq = 0; nq < 4; nq++) {
                uint32_t kh4[4], kl4[4];
                __half* kp = Kh + (nq * 16 + kvrow) * 72 + dcol;
                LDSM4(kh4, kp);
                LDSM4(kl4, kp + 4608);
                #pragma unroll
                for (int mi = 0; mi < 2; mi++)
                    #pragma unroll
                    for (int hb = 0; hb < 2; hb++) {
                        float* sd = sreg[mi][nq * 2 + hb];
                        const uint32_t* bh = kh4 + hb * 2;
                        const uint32_t* bl = kl4 + hb * 2;
                        hmma(sd, qh[mi], bh);
                        hmma(sd, qh[mi], bl);
                        hmma(sd, ql[mi], bh);
                    }
            }
        }

        // ---- mask add (scaled into log2 domain) ----
        if (maskFull) {
            #pragma unroll
            for (int mi = 0; mi < 2; mi++) {
                const int row0 = q0 + wm + mi * 16 + g;
                #pragma unroll
                for (int nj = 0; nj < 8; nj++) {
                    float2 m0 = *(const float2*)(mask + (size_t)row0 * Tk + kr0 + nj * 8 + t * 2);
                    float2 m1 = *(const float2*)(mask + (size_t)(row0 + 8) * Tk + kr0 + nj * 8 + t * 2);
                    sreg[mi][nj][0] = fmaf(m0.x, LOG2E, sreg[mi][nj][0]);
                    sreg[mi][nj][1] = fmaf(m0.y, LOG2E, sreg[mi][nj][1]);
                    sreg[mi][nj][2] = fmaf(m1.x, LOG2E, sreg[mi][nj][2]);
                    sreg[mi][nj][3] = fmaf(m1.y, LOG2E, sreg[mi][nj][3]);
                }
            }
        } else {
            #pragma unroll
            for (int nj = 0; nj < 8; nj++) {
                float2 mv = *(const float2*)(mask + kr0 + nj * 8 + t * 2);
                #pragma unroll
                for (int mi = 0; mi < 2; mi++) {
                    sreg[mi][nj][0] = fmaf(mv.x, LOG2E, sreg[mi][nj][0]);
                    sreg[mi][nj][1] = fmaf(mv.y, LOG2E, sreg[mi][nj][1]);
                    sreg[mi][nj][2] = fmaf(mv.x, LOG2E, sreg[mi][nj][2]);
                    sreg[mi][nj][3] = fmaf(mv.y, LOG2E, sreg[mi][nj][3]);
                }
            }
        }

        // ---- online softmax in log2 domain (4 row-slots: mi*2 + rr) ----
        #pragma unroll
        for (int mi = 0; mi < 2; mi++)
            #pragma unroll
            for (int rr = 0; rr < 2; rr++) {
                const int r = mi * 2 + rr;
                float tm = -1e30f;
                #pragma unroll
                for (int nj = 0; nj < 8; nj++)
                    tm = fmaxf(tm, fmaxf(sreg[mi][nj][rr * 2], sreg[mi][nj][rr * 2 + 1]));
                tm = fmaxf(tm, __shfl_xor_sync(0xffffffffu, tm, 1));
                tm = fmaxf(tm, __shfl_xor_sync(0xffffffffu, tm, 2));
                float nm = fmaxf(m_run[r], tm);
                float sc = ex2(m_run[r] - nm);
                float rs = 0.f;
                #pragma unroll
                for (int nj = 0; nj < 8; nj++) {
                    float p0 = ex2(sreg[mi][nj][rr * 2] - nm);
                    float p1 = ex2(sreg[mi][nj][rr * 2 + 1] - nm);
                    sreg[mi][nj][rr * 2] = p0; sreg[mi][nj][rr * 2 + 1] = p1;
                    rs += p0 + p1;
                }
                rs += __shfl_xor_sync(0xffffffffu, rs, 1);
                rs += __shfl_xor_sync(0xffffffffu, rs, 2);
                l_run[r] = l_run[r] * sc + rs;
                m_run[r] = nm;
                #pragma unroll
                for (int nj = 0; nj < 8; nj++) {
                    oacc[mi][nj][rr * 2] *= sc;
                    oacc[mi][nj][rr * 2 + 1] *= sc;
                }
            }

        // ---- STS V pairs from rkv (pure copy) ----
        #pragma unroll
        for (int j = 0; j < 8; j++) {
            int idx = tid + j * 128;
            int kr = idx >> 4, dq = idx & 15;
            *(uint2*)(Vh + kr * 72 + dq * 4) = rkv[j];
            *(uint2*)(Vh + 4608 + kr * 72 + dq * 4) = rkv[j + 8];
        }
        __syncthreads();   // V ready; all warps past S(c)

        // ---- LDG K pairs chunk c+1 (latency hidden by PV) ----
        if (c + 1 < NCH) {
            const int kn0 = kbase + (c + 1) * 64;
            #pragma unroll
            for (int j = 0; j < 8; j++) {
                int idx = tid + j * 128;
                size_t off = (size_t)(kn0 + (idx >> 4)) * EE + hc + (idx & 15) * 4;
                rkv[j]     = *(const uint2*)(Kh_g + off);
                rkv[j + 8] = *(const uint2*)(Kl_g + off);
            }
        }

        // ---- O += P @ V ----
        #pragma unroll
        for (int ks = 0; ks < 4; ks++) {
            uint32_t ph[2][4], pl[2][4];
            #pragma unroll
            for (int mi = 0; mi < 2; mi++) {
                split2(sreg[mi][2 * ks][0],     sreg[mi][2 * ks][1],     ph[mi][0], pl[mi][0]);
                split2(sreg[mi][2 * ks][2],     sreg[mi][2 * ks][3],     ph[mi][1], pl[mi][1]);
                split2(sreg[mi][2 * ks + 1][0], sreg[mi][2 * ks + 1][1], ph[mi][2], pl[mi][2]);
                split2(sreg[mi][2 * ks + 1][2], sreg[mi][2 * ks + 1][3], ph[mi][3], pl[mi][3]);
            }
            const int krow = ks * 16 + ((lane >> 3) & 1) * 8 + (lane & 7);
            const int nc0 = ((lane >> 4) & 1) * 8;
            #pragma unroll
            for (int nq = 0; nq < 4; nq++) {
                uint32_t vh4[4], vl4[4];
                __half* vp = Vh + krow * 72 + nq * 16 + nc0;
                LDSM4T(vh4, vp);
                LDSM4T(vl4, vp + 4608);
                #pragma unroll
                for (int mi = 0; mi < 2; mi++)
                    #pragma unroll
                    for (int hb = 0; hb < 2; hb++) {
                        float* od = oacc[mi][nq * 2 + hb];
                        const uint32_t* bh = vh4 + hb * 2;
                        const uint32_t* bl = vl4 + hb * 2;
                        hmma(od, ph[mi], bh);
                        hmma(od, ph[mi], bl);
                        hmma(od, pl[mi], bh);
                    }
            }
        }
    }

    // epilogue: unnormalized partials + (m, l)
    #pragma unroll
    for (int mi = 0; mi < 2; mi++) {
        const int row = q0 + wm + mi * 16 + g;
        #pragma unroll
        for (int nj = 0; nj < 8; nj++) {
            const int col = hc + nj * 8 + t * 2;
            *(float2*)(op + (size_t)row * EE + col) =
                make_float2(oacc[mi][nj][0], oacc[mi][nj][1]);
            *(float2*)(op + (size_t)(row + 8) * EE + col) =
                make_float2(oacc[mi][nj][2], oacc[mi][nj][3]);
        }
        if (t == 0) {
            const size_t base = ((size_t)s * NH + blockIdx.y) * T2;
            ml[(base + row) * 2 + 0] = m_run[mi * 2];
            ml[(base + row) * 2 + 1] = l_run[mi * 2];
            ml[(base + row + 8) * 2 + 0] = m_run[mi * 2 + 1];
            ml[(base + row + 8) * 2 + 1] = l_run[mi * 2 + 1];
        }
    }
}

// ---------------- out = LN(relu(h + a [+ a2])); also emits log2e-scaled pairs
__global__ __launch_bounds__(128) void add_relu_ln(
    const float* __restrict__ h, const float* __restrict__ a,
    const float* __restrict__ a2,
    const float* __restrict__ g, const float* __restrict__ b,
    float* __restrict__ out, __half* __restrict__ oh, __half* __restrict__ ol)
{
    __shared__ float red[4];
    const int row = blockIdx.x;
    const int tid = threadIdx.x;
    const int c = tid * 4;

    float4 hv = *(const float4*)(h + (size_t)row * EE + c);
    float4 av = *(const float4*)(a + (size_t)row * EE + c);
    if (a2) {
        float4 a2v = *(const float4*)(a2 + (size_t)row * EE + c);
        av.x += a2v.x; av.y += a2v.y; av.z += a2v.z; av.w += a2v.w;
    }
    float v[4] = { fmaxf(hv.x + av.x, 0.f), fmaxf(hv.y + av.y, 0.f),
                   fmaxf(hv.z + av.z, 0.f), fmaxf(hv.w + av.w, 0.f) };

    float s = v[0] + v[1] + v[2] + v[3];
    #pragma unroll
    for (int m = 16; m; m >>= 1) s += __shfl_xor_sync(0xffffffffu, s, m);
    if ((tid & 31) == 0) red[tid >> 5] = s;
    __syncthreads();
    float mean = (red[0] + red[1] + red[2] + red[3]) * (1.f / EE);
    __syncthreads();

    float d = 0.f;
    #pragma unroll
    for (int j = 0; j < 4; j++) { float tt = v[j] - mean; d += tt * tt; }
    #pragma unroll
    for (int m = 16; m; m >>= 1) d += __shfl_xor_sync(0xffffffffu, d, m);
    if ((tid & 31) == 0) red[tid >> 5] = d;
    __syncthreads();
    float var = (red[0] + red[1] + red[2] + red[3]) * (1.f / EE);
    float rstd = rsqrtf(var + 1e-5f);

    float4 gv = *(const float4*)(g + c);
    float4 bv = *(const float4*)(b + c);
    float4 w = make_float4((v[0] - mean) * rstd * gv.x + bv.x,
                           (v[1] - mean) * rstd * gv.y + bv.y,
                           (v[2] - mean) * rstd * gv.z + bv.z,
                           (v[3] - mean) * rstd * gv.w + bv.w);
    *(float4*)(out + (size_t)row * EE + c) = w;
    uint32_t h01, l01, h23, l23;
    split2(w.x * LOG2E, w.y * LOG2E, h01, l01);
    split2(w.z * LOG2E, w.w * LOG2E, h23, l23);
    *(uint2*)(oh + (size_t)row * EE + c) = make_uint2(h01, h23);
    *(uint2*)(ol + (size_t)row * EE + c) = make_uint2(l01, l23);
}

// ---------------- launch ----------------
extern "C" void kernel_launch(void* const* d_in, const int* in_sizes, int n_in,
                              void* d_out, int out_size)
{
    (void)in_sizes; (void)n_in; (void)out_size;
    const float* x      = (const float*)d_in[0];
    const float* enc    = (const float*)d_in[1];
    const float* am     = (const float*)d_in[2];
    const float* em     = (const float*)d_in[3];
    const float* k_w    = (const float*)d_in[4];
    const float* k_b    = (const float*)d_in[5];
    const float* v_w    = (const float*)d_in[6];
    const float* v_b    = (const float*)d_in[7];
    const float* sa_q_w = (const float*)d_in[8];  const float* sa_q_b = (const float*)d_in[9];
    const float* sa_k_w = (const float*)d_in[10]; const float* sa_k_b = (const float*)d_in[11];
    const float* sa_v_w = (const float*)d_in[12]; const float* sa_v_b = (const float*)d_in[13];
    const float* sa_o_w = (const float*)d_in[14]; const float* sa_o_b = (const float*)d_in[15];
    const float* n1_g   = (const float*)d_in[16]; const float* n1_b   = (const float*)d_in[17];
    const float* ca_o_w = (const float*)d_in[18]; const float* ca_o_b = (const float*)d_in[19];
    const float* n2_g   = (const float*)d_in[20]; const float* n2_b   = (const float*)d_in[21];
    const float* f1_w   = (const float*)d_in[22]; const float* f1_b   = (const float*)d_in[23];
    const float* f2_w   = (const float*)d_in[24]; const float* f2_b   = (const float*)d_in[25];
    const float* n3_g   = (const float*)d_in[26]; const float* n3_b   = (const float*)d_in[27];

    float *h, *proj, *proj2, *ffn, *op, *ml, *mlw, *zb;
    cudaGetSymbolAddress((void**)&h,     g_h);
    cudaGetSymbolAddress((void**)&proj,  g_proj);
    cudaGetSymbolAddress((void**)&proj2, g_proj2);
    cudaGetSymbolAddress((void**)&ffn,   g_ffn);
    cudaGetSymbolAddress((void**)&op,    g_op);
    cudaGetSymbolAddress((void**)&ml,    g_ml);
    cudaGetSymbolAddress((void**)&mlw,   g_mlw);
    cudaGetSymbolAddress((void**)&zb,    g_zb);
    __half *qh, *ql, *kh, *kl, *vh, *vl, *hh, *hl, *Ksh, *Ksl, *Vsh, *Vsl;
    cudaGetSymbolAddress((void**)&qh, g_qh);   cudaGetSymbolAddress((void**)&ql, g_ql);
    cudaGetSymbolAddress((void**)&kh, g_kh);   cudaGetSymbolAddress((void**)&kl, g_kl);
    cudaGetSymbolAddress((void**)&vh, g_vh);   cudaGetSymbolAddress((void**)&vl, g_vl);
    cudaGetSymbolAddress((void**)&hh, g_hh);   cudaGetSymbolAddress((void**)&hl, g_hl);
    cudaGetSymbolAddress((void**)&Ksh, g_Ksh); cudaGetSymbolAddress((void**)&Ksl, g_Ksl);
    cudaGetSymbolAddress((void**)&Vsh, g_Vsh); cudaGetSymbolAddress((void**)&Vsl, g_Vsl);

    cudaFuncSetAttribute((const void*)attn_mma,
                         cudaFuncAttributeMaxDynamicSharedMemorySize, ASMEM);
    cudaFuncSetAttribute((const void*)gemm_mma<0>,
                         cudaFuncAttributeMaxDynamicSharedMemorySize, GSMEM);
    cudaFuncSetAttribute((const void*)gemm_mma<1>,
                         cudaFuncAttributeMaxDynamicSharedMemorySize, GSMEM);

    const dim3 gP (EE / 64, T2 / 128, 1);   // single-output GEMMs
    const dim3 gP3(EE / 64, T2 / 128, 3);   // fused QKV
    const dim3 gP2(EE / 64, T2 / 128, 2);   // fused Ks/Vs and split-K f2
    const dim3 gF (FF / 64, T2 / 128, 1);   // f1
    const dim3 gA (T2 / 128, NH, 2);        // attention split-KV
    const dim3 gW (NH * T2 / 256, 1, 1);    // mlw

    copyk<<<T2 * EE / 1024, 256>>>(x, h);
    {
        GOut oK{k_w, k_b, nullptr, Ksh, Ksl, 1.f};
        GOut oV{v_w, v_b, nullptr, Vsh, Vsl, 1.f};
        gemm_mma<0><<<gP2, 256, GSMEM>>>(enc, nullptr, oK, oV, oV, EE, EE, EE, 0, 0);
    }

    for (int l = 0; l < NL; l++) {
        const size_t wo = (size_t)l * EE * EE, bo = (size_t)l * EE;
        // self-attention: fused QKV projections -> pair outputs (Q scaled by log2e)
        {
            GOut oQ{sa_q_w + wo, sa_q_b + bo, nullptr, qh, ql, LOG2E};
            GOut oKk{sa_k_w + wo, sa_k_b + bo, nullptr, kh, kl, 1.f};
            GOut oVv{sa_v_w + wo, sa_v_b + bo, nullptr, vh, vl, 1.f};
            gemm_mma<0><<<gP3, 256, GSMEM>>>(h, nullptr, oQ, oKk, oVv, EE, EE, EE, 0, 0);
        }
        attn_mma<<<gA, 128, ASMEM>>>(qh, ql, kh, kl, vh, vl, am, op, ml, T2, 1);
        mlw_kernel<<<gW, 256>>>(ml, mlw);
        {
            GOut oO{sa_o_w + wo, sa_o_b + bo, proj, nullptr, nullptr, 1.f};
            gemm_mma<1><<<gP, 256, GSMEM>>>(op, mlw, oO, oO, oO, EE, EE, EE, 0, 1);
        }
        add_relu_ln<<<T2, 128>>>(h, proj, nullptr, n1_g + bo, n1_b + bo, h, hh, hl);
        // cross-attention (Q = h pairs, pre-scaled by log2e)
        attn_mma<<<gA, 128, ASMEM>>>(hh, hl, Ksh, Ksl, Vsh, Vsl, em, op, ml, T1, 0);
        mlw_kernel<<<gW, 256>>>(ml, mlw);
        {
            GOut oO{ca_o_w + wo, ca_o_b + bo, proj, nullptr, nullptr, 1.f};
            gemm_mma<1><<<gP, 256, GSMEM>>>(op, mlw, oO, oO, oO, EE, EE, EE, 0, 1);
        }
        add_relu_ln<<<T2, 128>>>(h, proj, nullptr, n2_g + bo, n2_b + bo, h, hh, hl);
        // FFN: f1 full-K, f2 split-K x2 (partials summed in add_relu_ln)
        {
            GOut oF{f1_w + (size_t)l * EE * FF, f1_b + (size_t)l * FF, ffn, nullptr, nullptr, 1.f};
            gemm_mma<0><<<gF, 256, GSMEM>>>(h, nullptr, oF, oF, oF, FF, EE, EE, 0, 1);
        }
        {
            GOut o0{f2_w + (size_t)l * FF * EE,                     f2_b + bo, proj,  nullptr, nullptr, 1.f};
            GOut o1{f2_w + (size_t)l * FF * EE + (size_t)1024 * EE, zb,        proj2, nullptr, nullptr, 1.f};
            gemm_mma<0><<<gP2, 256, GSMEM>>>(ffn, nullptr, o0, o1, o0, EE, FF, 1024, 1024, 0);
        }
        add_relu_ln<<<T2, 128>>>(h, proj, proj2, n3_g + bo, n3_b + bo, h, hh, hl);
    }

    copyk<<<T2 * EE / 1024, 256>>>(h, (float*)d_out);
}

// round 10
// speedup vs baseline: 1.1229x; 1.1229x over previous
#include <cuda_runtime.h>
#include <cuda_fp16.h>
#include <cstdint>

#define T2 2048
#define T1 2048
#define EE 512
#define FF 2048
#define NL 4
#define NH 8
#define LOG2E 1.4426950408889634f

// ---------------- scratch (device globals; allocation-free) ----------------
__device__ float g_h    [T2*EE];
__device__ float g_q    [T2*EE];
__device__ float g_k    [T2*EE];
__device__ float g_v    [T2*EE];
__device__ float g_proj [T2*EE];
__device__ float g_proj2[T2*EE];
__device__ float g_ffn  [T2*FF];
__device__ float g_Ks   [T1*EE];
__device__ float g_Vs   [T1*EE];
__device__ float g_op   [2*T2*EE];      // split-KV partial O (unnormalized)
__device__ float g_ml   [2*NH*T2*2];    // split-KV per-row (m log2-dom, l)
__device__ float g_mlw  [2*NH*T2];      // combine weights w0', w1'
__device__ float g_zb   [FF];           // zero bias (zero-initialized)

// ---------------- helpers ----------------
__device__ __forceinline__ void hmma(float* d, const uint32_t* a, const uint32_t* b) {
    asm volatile(
        "mma.sync.aligned.m16n8k16.row.col.f32.f16.f16.f32 "
        "{%0,%1,%2,%3}, {%4,%5,%6,%7}, {%8,%9}, {%0,%1,%2,%3};"
        : "+f"(d[0]), "+f"(d[1]), "+f"(d[2]), "+f"(d[3])
        : "r"(a[0]), "r"(a[1]), "r"(a[2]), "r"(a[3]), "r"(b[0]), "r"(b[1]));
}
#define LDSM4(R, PTR) do {                                                     \
    uint32_t a_ = (uint32_t)__cvta_generic_to_shared(PTR);                     \
    asm volatile("ldmatrix.sync.aligned.m8n8.x4.shared.b16 {%0,%1,%2,%3}, [%4];" \
        : "=r"((R)[0]), "=r"((R)[1]), "=r"((R)[2]), "=r"((R)[3]) : "r"(a_));   \
} while (0)
#define LDSM4T(R, PTR) do {                                                    \
    uint32_t a_ = (uint32_t)__cvta_generic_to_shared(PTR);                     \
    asm volatile("ldmatrix.sync.aligned.m8n8.x4.trans.shared.b16 {%0,%1,%2,%3}, [%4];" \
        : "=r"((R)[0]), "=r"((R)[1]), "=r"((R)[2]), "=r"((R)[3]) : "r"(a_));   \
} while (0)

__device__ __forceinline__ float ex2(float x) {
    float y;
    asm("ex2.approx.f32 %0, %1;" : "=f"(y) : "f"(x));
    return y;
}
__device__ __forceinline__ uint32_t packh2(float x, float y) {
    __half2 h = __floats2half2_rn(x, y);
    return *reinterpret_cast<uint32_t*>(&h);
}
// 2-term fp16 split: (x,y) -> hi pair + lo pair; x ≈ hi + lo to ~2.4e-7 rel.
__device__ __forceinline__ void split2(float x, float y, uint32_t& hi, uint32_t& lo) {
    float hx = __half2float(__float2half_rn(x));
    float hy = __half2float(__float2half_rn(y));
    hi = packh2(hx, hy);
    lo = packh2(x - hx, y - hy);
}

// ---------------- elementwise copy ----------------
__global__ void copyk(const float* __restrict__ in, float* __restrict__ out) {
    size_t i = ((size_t)blockIdx.x * blockDim.x + threadIdx.x) * 4;
    *(float4*)(out + i) = *(const float4*)(in + i);
}

// ---------------- ml -> combine weights (m in log2 domain) ----------------
__global__ __launch_bounds__(256) void mlw_kernel(
    const float* __restrict__ ml, float* __restrict__ mlw)
{
    const int i = blockIdx.x * 256 + threadIdx.x;   // i = head*T2 + row
    float m0 = ml[i * 2 + 0];
    float l0 = ml[i * 2 + 1];
    float m1 = ml[(NH * T2 + i) * 2 + 0];
    float l1 = ml[(NH * T2 + i) * 2 + 1];
    float m = fmaxf(m0, m1);
    float w0 = ex2(m0 - m), w1 = ex2(m1 - m);
    float inv = 1.f / (l0 * w0 + l1 * w1);
    mlw[i] = w0 * inv;
    mlw[NH * T2 + i] = w1 * inv;
}

// ---------------- fp16-split GEMM: C = act(A @ B + bias), tile 128x64 -------
// 256 threads, 8 warps (4x2), warp 32x32, BK=32, 2-stage register pipeline.
// CMB=1: A is split-KV partial base (op); combine with mlw during load.
// blockIdx.z selects (B,bias,C) triple (fused QKV / split-K; hoffZ = head offset).
// stage halves: Ah[128][40]@0 Al@5120 Bh[32][72]@10240 Bl@12544; GST=14848.
#define GST 14848
#define GSMEM (2 * GST * 2)   // 59392 B

template<int CMB>
__global__ __launch_bounds__(256, 2) void gemm_mma(
    const float* __restrict__ A, const float* __restrict__ mlw,
    const float* __restrict__ B0, const float* __restrict__ b0, float* __restrict__ C0,
    const float* __restrict__ B1, const float* __restrict__ b1, float* __restrict__ C1,
    const float* __restrict__ B2, const float* __restrict__ b2, float* __restrict__ C2,
    int N, int lda, int kCnt, int aoffZ, int hoffZ, int act)
{
    extern __shared__ __half hsm[];
    const int z = blockIdx.z;
    const float* B    = (z == 0) ? B0 : ((z == 1) ? B1 : B2);
    const float* bias = (z == 0) ? b0 : ((z == 1) ? b1 : b2);
    float*       C    = (z == 0) ? C0 : ((z == 1) ? C1 : C2);
    const float* Az   = A + (size_t)z * aoffZ;
    const int headOff = z * hoffZ;

    const int tid = threadIdx.x;
    const int wid = tid >> 5, lane = tid & 31;
    const int g = lane >> 2, t = lane & 3;
    const int bm = blockIdx.y * 128, bn = blockIdx.x * 64;
    const int wm = (wid >> 1) * 32, wn = (wid & 1) * 32;

    float acc[2][4][4];
    #pragma unroll
    for (int mi = 0; mi < 2; mi++)
        #pragma unroll
        for (int nj = 0; nj < 4; nj++)
            #pragma unroll
            for (int r = 0; r < 4; r++) acc[mi][nj][r] = 0.f;

    const int NC = kCnt >> 5;
    float4 ra[4], rb[2];

    #define GLDG(c) do {                                                        \
        _Pragma("unroll")                                                       \
        for (int j_ = 0; j_ < 4; j_++) {                                        \
            int idx_ = tid + j_ * 256;                                          \
            int row_ = bm + (idx_ >> 3);                                        \
            int col_ = (c) * 32 + (idx_ & 7) * 4;                               \
            if (CMB) {                                                          \
                int head_ = ((c) >> 1) + headOff;                               \
                float w0_ = mlw[head_ * T2 + row_];                             \
                float w1_ = mlw[NH * T2 + head_ * T2 + row_];                   \
                float4 a0_ = *(const float4*)(Az + (size_t)row_ * EE + col_);   \
                float4 a1_ = *(const float4*)(Az + (size_t)T2 * EE              \
                                              + (size_t)row_ * EE + col_);      \
                ra[j_].x = a0_.x * w0_ + a1_.x * w1_;                           \
                ra[j_].y = a0_.y * w0_ + a1_.y * w1_;                           \
                ra[j_].z = a0_.z * w0_ + a1_.z * w1_;                           \
                ra[j_].w = a0_.w * w0_ + a1_.w * w1_;                           \
            } else {                                                            \
                ra[j_] = *(const float4*)(Az + (size_t)row_ * lda + col_);      \
            }                                                                   \
        }                                                                       \
        _Pragma("unroll")                                                       \
        for (int j_ = 0; j_ < 2; j_++) {                                        \
            int idx_ = tid + j_ * 256;                                          \
            rb[j_] = *(const float4*)(B + (size_t)((c) * 32 + (idx_ >> 4)) * N  \
                                      + bn + (idx_ & 15) * 4);                  \
        }                                                                       \
    } while (0)

    #define GSTS(s) do {                                                        \
        __half* st_ = hsm + (s) * GST;                                          \
        _Pragma("unroll")                                                       \
        for (int j_ = 0; j_ < 4; j_++) {                                        \
            int idx_ = tid + j_ * 256;                                          \
            int m_ = idx_ >> 3, kq_ = idx_ & 7;                                 \
            uint32_t h01, l01, h23, l23;                                        \
            split2(ra[j_].x, ra[j_].y, h01, l01);                               \
            split2(ra[j_].z, ra[j_].w, h23, l23);                               \
            *(uint2*)(st_ + m_ * 40 + kq_ * 4) = make_uint2(h01, h23);          \
            *(uint2*)(st_ + 5120 + m_ * 40 + kq_ * 4) = make_uint2(l01, l23);   \
        }                                                                       \
        _Pragma("unroll")                                                       \
        for (int j_ = 0; j_ < 2; j_++) {                                        \
            int idx_ = tid + j_ * 256;                                          \
            int k_ = idx_ >> 4, nq_ = idx_ & 15;                                \
            uint32_t h01, l01, h23, l23;                                        \
            split2(rb[j_].x, rb[j_].y, h01, l01);                               \
            split2(rb[j_].z, rb[j_].w, h23, l23);                               \
            *(uint2*)(st_ + 10240 + k_ * 72 + nq_ * 4) = make_uint2(h01, h23);  \
            *(uint2*)(st_ + 12544 + k_ * 72 + nq_ * 4) = make_uint2(l01, l23);  \
        }                                                                       \
    } while (0)

    GLDG(0); GSTS(0);
    if (NC > 1) GLDG(1);
    __syncthreads();

    for (int c = 0; c < NC; c++) {
        if (c + 1 < NC) GSTS((c + 1) & 1);
        if (c + 2 < NC) GLDG(c + 2);

        __half* st = hsm + (c & 1) * GST;
        #pragma unroll
        for (int ks = 0; ks < 2; ks++) {
            const int kb = ks * 16;
            uint32_t Ahf[2][4], Alf[2][4], Bhf[2][4], Blf[2][4];
            const int arow = (lane & 15), acol = kb + (lane >> 4) * 8;
            #pragma unroll
            for (int mi = 0; mi < 2; mi++) {
                __half* ap = st + (wm + mi * 16 + arow) * 40 + acol;
                LDSM4(Ahf[mi], ap);
                LDSM4(Alf[mi], ap + 5120);
            }
            const int krow = kb + ((lane >> 3) & 1) * 8 + (lane & 7);
            #pragma unroll
            for (int nq = 0; nq < 2; nq++) {
                const int ncol = wn + nq * 16 + ((lane >> 4) & 1) * 8;
                __half* bp = st + 10240 + krow * 72 + ncol;
                LDSM4T(Bhf[nq], bp);
                LDSM4T(Blf[nq], bp + 2304);
            }
            #pragma unroll
            for (int mi = 0; mi < 2; mi++)
                #pragma unroll
                for (int nj = 0; nj < 4; nj++) {
                    const uint32_t* bh = &Bhf[nj >> 1][(nj & 1) * 2];
                    const uint32_t* bl = &Blf[nj >> 1][(nj & 1) * 2];
                    hmma(acc[mi][nj], Ahf[mi], bh);
                    hmma(acc[mi][nj], Ahf[mi], bl);
                    hmma(acc[mi][nj], Alf[mi], bh);
                }
        }
        __syncthreads();
    }

    #pragma unroll
    for (int mi = 0; mi < 2; mi++) {
        #pragma unroll
        for (int nj = 0; nj < 4; nj++) {
            const int row = bm + wm + mi * 16 + g;
            const int col = bn + wn + nj * 8 + t * 2;
            float2 bv = *(const float2*)(bias + col);
            float2 w0, w1;
            w0.x = acc[mi][nj][0] + bv.x; w0.y = acc[mi][nj][1] + bv.y;
            w1.x = acc[mi][nj][2] + bv.x; w1.y = acc[mi][nj][3] + bv.y;
            if (act) {
                w0.x = fmaxf(w0.x, 0.f); w0.y = fmaxf(w0.y, 0.f);
                w1.x = fmaxf(w1.x, 0.f); w1.y = fmaxf(w1.y, 0.f);
            }
            *(float2*)(C + (size_t)row * N + col) = w0;
            *(float2*)(C + (size_t)(row + 8) * N + col) = w1;
        }
    }
    #undef GLDG
    #undef GSTS
}

// ---------------- fp16-split flash attention, split-KV x2 -------------------
// log2-domain softmax: Q pre-scaled by log2e at STS, ex2 for exps.
// PV uses 2-MMA (P rounded to fp16; V kept split): O += Ph*Vh + Ph*Vl.
// CTA: 128 q-rows x 1 head x 1 KV-half; 4 warps x 32 q-rows; KV chunks of 64.
// smem halves: Qh[128][72]@0 Ql@9216 Kh[64][72]@18432 Kl@23040 Vh@27648 Vl@32256
#define ASMEM 73728

__global__ __launch_bounds__(128, 2) void attn_mma(
    const float* __restrict__ Q, const float* __restrict__ K,
    const float* __restrict__ V, const float* __restrict__ mask,
    float* __restrict__ Opart, float* __restrict__ ml,
    int Tk, int maskFull)
{
    extern __shared__ __half hsm[];
    __half* Qh = hsm;              // lo at +9216
    __half* Kh = hsm + 18432;      // lo at +4608
    __half* Vh = hsm + 27648;      // lo at +4608

    const int tid = threadIdx.x;
    const int wid = tid >> 5, lane = tid & 31;
    const int g = lane >> 2, t = lane & 3;
    const int q0 = blockIdx.x * 128, hc = blockIdx.y * 64;
    const int s = blockIdx.z;
    const int kbase = s * (Tk >> 1);
    const int wm = wid * 32;
    float* op = Opart + (size_t)s * T2 * EE;

    // Q tile 128x64 -> split fp16, pre-scaled by log2e
    #pragma unroll
    for (int j = 0; j < 16; j++) {
        int idx = tid + j * 128;
        int r = idx >> 4, dq = idx & 15;
        float4 qv = *(const float4*)(Q + (size_t)(q0 + r) * EE + hc + dq * 4);
        uint32_t h01, l01, h23, l23;
        split2(qv.x * LOG2E, qv.y * LOG2E, h01, l01);
        split2(qv.z * LOG2E, qv.w * LOG2E, h23, l23);
        *(uint2*)(Qh + r * 72 + dq * 4) = make_uint2(h01, h23);
        *(uint2*)(Qh + 9216 + r * 72 + dq * 4) = make_uint2(l01, l23);
    }

    // shared K/V staging registers (disjoint lifetimes)
    float4 rkv[8];
    #pragma unroll
    for (int j = 0; j < 8; j++) {
        int idx = tid + j * 128;
        rkv[j] = *(const float4*)(K + (size_t)(kbase + (idx >> 4)) * EE + hc + (idx & 15) * 4);
    }

    float m_run[4], l_run[4];
    #pragma unroll
    for (int r = 0; r < 4; r++) { m_run[r] = -1e30f; l_run[r] = 0.f; }
    float oacc[2][8][4];
    #pragma unroll
    for (int mi = 0; mi < 2; mi++)
        #pragma unroll
        for (int nj = 0; nj < 8; nj++)
            #pragma unroll
            for (int r = 0; r < 4; r++) oacc[mi][nj][r] = 0.f;

    const int NCH = Tk >> 7;    // chunks of 64 within this half
    for (int c = 0; c < NCH; c++) {
        const int kr0 = kbase + c * 64;

        // ---- STS K (split) from rkv ----
        #pragma unroll
        for (int j = 0; j < 8; j++) {
            int idx = tid + j * 128;
            int kr = idx >> 4, dq = idx & 15;
            uint32_t h01, l01, h23, l23;
            split2(rkv[j].x, rkv[j].y, h01, l01); split2(rkv[j].z, rkv[j].w, h23, l23);
            *(uint2*)(Kh + kr * 72 + dq * 4) = make_uint2(h01, h23);
            *(uint2*)(Kh + 4608 + kr * 72 + dq * 4) = make_uint2(l01, l23);
        }
        __syncthreads();   // K (and Q on c=0) ready; all warps past PV(c-1)

        // ---- LDG V chunk c (latency hidden by S-MMA) ----
        #pragma unroll
        for (int j = 0; j < 8; j++) {
            int idx = tid + j * 128;
            rkv[j] = *(const float4*)(V + (size_t)(kr0 + (idx >> 4)) * EE + hc + (idx & 15) * 4);
        }

        // ---- S = Q @ K^T (log2 domain) ----
        float sreg[2][8][4];
        #pragma unroll
        for (int mi = 0; mi < 2; mi++)
            #pragma unroll
            for (int nj = 0; nj < 8; nj++)
                #pragma unroll
                for (int r = 0; r < 4; r++) sreg[mi][nj][r] = 0.f;

        #pragma unroll
        for (int ks = 0; ks < 4; ks++) {
            uint32_t qh[2][4], ql[2][4];
            #pragma unroll
            for (int mi = 0; mi < 2; mi++) {
                __half* qp = Qh + (wm + mi * 16 + (lane & 15)) * 72 + ks * 16 + (lane >> 4) * 8;
                LDSM4(qh[mi], qp);
                LDSM4(ql[mi], qp + 9216);
            }
            const int kvrow = ((lane >> 4) & 1) * 8 + (lane & 7);
            const int dcol = ks * 16 + ((lane >> 3) & 1) * 8;
            #pragma unroll
            for (int nq = 0; nq < 4; nq++) {
                uint32_t kh4[4], kl4[4];
                __half* kp = Kh + (nq * 16 + kvrow) * 72 + dcol;
                LDSM4(kh4, kp);
                LDSM4(kl4, kp + 4608);
                #pragma unroll
                for (int mi = 0; mi < 2; mi++)
                    #pragma unroll
                    for (int hb = 0; hb < 2; hb++) {
                        float* sd = sreg[mi][nq * 2 + hb];
                        const uint32_t* bh = kh4 + hb * 2;
                        const uint32_t* bl = kl4 + hb * 2;
                        hmma(sd, qh[mi], bh);
                        hmma(sd, qh[mi], bl);
                        hmma(sd, ql[mi], bh);
                    }
            }
        }

        // ---- mask add (scaled into log2 domain) ----
        if (maskFull) {
            #pragma unroll
            for (int mi = 0; mi < 2; mi++) {
                const int row0 = q0 + wm + mi * 16 + g;
                #pragma unroll
                for (int nj = 0; nj < 8; nj++) {
                    float2 m0 = *(const float2*)(mask + (size_t)row0 * Tk + kr0 + nj * 8 + t * 2);
                    float2 m1 = *(const float2*)(mask + (size_t)(row0 + 8) * Tk + kr0 + nj * 8 + t * 2);
                    sreg[mi][nj][0] = fmaf(m0.x, LOG2E, sreg[mi][nj][0]);
                    sreg[mi][nj][1] = fmaf(m0.y, LOG2E, sreg[mi][nj][1]);
                    sreg[mi][nj][2] = fmaf(m1.x, LOG2E, sreg[mi][nj][2]);
                    sreg[mi][nj][3] = fmaf(m1.y, LOG2E, sreg[mi][nj][3]);
                }
            }
        } else {
            #pragma unroll
            for (int nj = 0; nj < 8; nj++) {
                float2 mv = *(const float2*)(mask + kr0 + nj * 8 + t * 2);
                #pragma unroll
                for (int mi = 0; mi < 2; mi++) {
                    sreg[mi][nj][0] = fmaf(mv.x, LOG2E, sreg[mi][nj][0]);
                    sreg[mi][nj][1] = fmaf(mv.y, LOG2E, sreg[mi][nj][1]);
                    sreg[mi][nj][2] = fmaf(mv.x, LOG2E, sreg[mi][nj][2]);
                    sreg[mi][nj][3] = fmaf(mv.y, LOG2E, sreg[mi][nj][3]);
                }
            }
        }

        // ---- online softmax in log2 domain (4 row-slots: mi*2 + rr) ----
        #pragma unroll
        for (int mi = 0; mi < 2; mi++)
            #pragma unroll
            for (int rr = 0; rr < 2; rr++) {
                const int r = mi * 2 + rr;
                float tm = -1e30f;
                #pragma unroll
                for (int nj = 0; nj < 8; nj++)
                    tm = fmaxf(tm, fmaxf(sreg[mi][nj][rr * 2], sreg[mi][nj][rr * 2 + 1]));
                tm = fmaxf(tm, __shfl_xor_sync(0xffffffffu, tm, 1));
                tm = fmaxf(tm, __shfl_xor_sync(0xffffffffu, tm, 2));
                float nm = fmaxf(m_run[r], tm);
                float sc = ex2(m_run[r] - nm);
                float rs = 0.f;
                #pragma unroll
                for (int nj = 0; nj < 8; nj++) {
                    float p0 = ex2(sreg[mi][nj][rr * 2] - nm);
                    float p1 = ex2(sreg[mi][nj][rr * 2 + 1] - nm);
                    sreg[mi][nj][rr * 2] = p0; sreg[mi][nj][rr * 2 + 1] = p1;
                    rs += p0 + p1;
                }
                rs += __shfl_xor_sync(0xffffffffu, rs, 1);
                rs += __shfl_xor_sync(0xffffffffu, rs, 2);
                l_run[r] = l_run[r] * sc + rs;
                m_run[r] = nm;
                #pragma unroll
                for (int nj = 0; nj < 8; nj++) {
                    oacc[mi][nj][rr * 2] *= sc;
                    oacc[mi][nj][rr * 2 + 1] *= sc;
                }
            }

        // ---- STS V (split) from rkv ----
        #pragma unroll
        for (int j = 0; j < 8; j++) {
            int idx = tid + j * 128;
            int kr = idx >> 4, dq = idx & 15;
            uint32_t h01, l01, h23, l23;
            split2(rkv[j].x, rkv[j].y, h01, l01); split2(rkv[j].z, rkv[j].w, h23, l23);
            *(uint2*)(Vh + kr * 72 + dq * 4) = make_uint2(h01, h23);
            *(uint2*)(Vh + 4608 + kr * 72 + dq * 4) = make_uint2(l01, l23);
        }
        __syncthreads();   // V ready; all warps past S(c)

        // ---- LDG K chunk c+1 (latency hidden by PV) ----
        if (c + 1 < NCH) {
            const int kn0 = kbase + (c + 1) * 64;
            #pragma unroll
            for (int j = 0; j < 8; j++) {
                int idx = tid + j * 128;
                rkv[j] = *(const float4*)(K + (size_t)(kn0 + (idx >> 4)) * EE + hc + (idx & 15) * 4);
            }
        }

        // ---- O += P @ V (2-MMA: P rounded to fp16, V split) ----
        #pragma unroll
        for (int ks = 0; ks < 4; ks++) {
            uint32_t ph[2][4];
            #pragma unroll
            for (int mi = 0; mi < 2; mi++) {
                ph[mi][0] = packh2(sreg[mi][2 * ks][0],     sreg[mi][2 * ks][1]);
                ph[mi][1] = packh2(sreg[mi][2 * ks][2],     sreg[mi][2 * ks][3]);
                ph[mi][2] = packh2(sreg[mi][2 * ks + 1][0], sreg[mi][2 * ks + 1][1]);
                ph[mi][3] = packh2(sreg[mi][2 * ks + 1][2], sreg[mi][2 * ks + 1][3]);
            }
            const int krow = ks * 16 + ((lane >> 3) & 1) * 8 + (lane & 7);
            const int nc0 = ((lane >> 4) & 1) * 8;
            #pragma unroll
            for (int nq = 0; nq < 4; nq++) {
                uint32_t vh4[4], vl4[4];
                __half* vp = Vh + krow * 72 + nq * 16 + nc0;
                LDSM4T(vh4, vp);
                LDSM4T(vl4, vp + 4608);
                #pragma unroll
                for (int mi = 0; mi < 2; mi++)
                    #pragma unroll
                    for (int hb = 0; hb < 2; hb++) {
                        float* od = oacc[mi][nq * 2 + hb];
                        hmma(od, ph[mi], vh4 + hb * 2);
                        hmma(od, ph[mi], vl4 + hb * 2);
                    }
            }
        }
    }

    // epilogue: unnormalized partials + (m, l)
    #pragma unroll
    for (int mi = 0; mi < 2; mi++) {
        const int row = q0 + wm + mi * 16 + g;
        #pragma unroll
        for (int nj = 0; nj < 8; nj++) {
            const int col = hc + nj * 8 + t * 2;
            *(float2*)(op + (size_t)row * EE + col) =
                make_float2(oacc[mi][nj][0], oacc[mi][nj][1]);
            *(float2*)(op + (size_t)(row + 8) * EE + col) =
                make_float2(oacc[mi][nj][2], oacc[mi][nj][3]);
        }
        if (t == 0) {
            const size_t base = ((size_t)s * NH + blockIdx.y) * T2;
            ml[(base + row) * 2 + 0] = m_run[mi * 2];
            ml[(base + row) * 2 + 1] = l_run[mi * 2];
            ml[(base + row + 8) * 2 + 0] = m_run[mi * 2 + 1];
            ml[(base + row + 8) * 2 + 1] = l_run[mi * 2 + 1];
        }
    }
}

// ---------------- out = LN(relu(h + f(a [+ a2]))) * g + b -------------------
// innerRelu=1: f = relu (for split-K O-projections); else f = identity.
__global__ __launch_bounds__(128) void add_relu_ln(
    const float* __restrict__ h, const float* __restrict__ a,
    const float* __restrict__ a2,
    const float* __restrict__ g, const float* __restrict__ b,
    float* __restrict__ out, int innerRelu)
{
    __shared__ float red[4];
    const int row = blockIdx.x;
    const int tid = threadIdx.x;
    const int c = tid * 4;

    float4 hv = *(const float4*)(h + (size_t)row * EE + c);
    float4 av = *(const float4*)(a + (size_t)row * EE + c);
    if (a2) {
        float4 a2v = *(const float4*)(a2 + (size_t)row * EE + c);
        av.x += a2v.x; av.y += a2v.y; av.z += a2v.z; av.w += a2v.w;
    }
    if (innerRelu) {
        av.x = fmaxf(av.x, 0.f); av.y = fmaxf(av.y, 0.f);
        av.z = fmaxf(av.z, 0.f); av.w = fmaxf(av.w, 0.f);
    }
    float v[4] = { fmaxf(hv.x + av.x, 0.f), fmaxf(hv.y + av.y, 0.f),
                   fmaxf(hv.z + av.z, 0.f), fmaxf(hv.w + av.w, 0.f) };

    float s = v[0] + v[1] + v[2] + v[3];
    #pragma unroll
    for (int m = 16; m; m >>= 1) s += __shfl_xor_sync(0xffffffffu, s, m);
    if ((tid & 31) == 0) red[tid >> 5] = s;
    __syncthreads();
    float mean = (red[0] + red[1] + red[2] + red[3]) * (1.f / EE);
    __syncthreads();

    float d = 0.f;
    #pragma unroll
    for (int j = 0; j < 4; j++) { float tt = v[j] - mean; d += tt * tt; }
    #pragma unroll
    for (int m = 16; m; m >>= 1) d += __shfl_xor_sync(0xffffffffu, d, m);
    if ((tid & 31) == 0) red[tid >> 5] = d;
    __syncthreads();
    float var = (red[0] + red[1] + red[2] + red[3]) * (1.f / EE);
    float rstd = rsqrtf(var + 1e-5f);

    float4 gv = *(const float4*)(g + c);
    float4 bv = *(const float4*)(b + c);
    float4 w = make_float4((v[0] - mean) * rstd * gv.x + bv.x,
                           (v[1] - mean) * rstd * gv.y + bv.y,
                           (v[2] - mean) * rstd * gv.z + bv.z,
                           (v[3] - mean) * rstd * gv.w + bv.w);
    *(float4*)(out + (size_t)row * EE + c) = w;
}

// ---------------- launch ----------------
extern "C" void kernel_launch(void* const* d_in, const int* in_sizes, int n_in,
                              void* d_out, int out_size)
{
    (void)in_sizes; (void)n_in; (void)out_size;
    const float* x      = (const float*)d_in[0];
    const float* enc    = (const float*)d_in[1];
    const float* am     = (const float*)d_in[2];
    const float* em     = (const float*)d_in[3];
    const float* k_w    = (const float*)d_in[4];
    const float* k_b    = (const float*)d_in[5];
    const float* v_w    = (const float*)d_in[6];
    const float* v_b    = (const float*)d_in[7];
    const float* sa_q_w = (const float*)d_in[8];  const float* sa_q_b = (const float*)d_in[9];
    const float* sa_k_w = (const float*)d_in[10]; const float* sa_k_b = (const float*)d_in[11];
    const float* sa_v_w = (const float*)d_in[12]; const float* sa_v_b = (const float*)d_in[13];
    const float* sa_o_w = (const float*)d_in[14]; const float* sa_o_b = (const float*)d_in[15];
    const float* n1_g   = (const float*)d_in[16]; const float* n1_b   = (const float*)d_in[17];
    const float* ca_o_w = (const float*)d_in[18]; const float* ca_o_b = (const float*)d_in[19];
    const float* n2_g   = (const float*)d_in[20]; const float* n2_b   = (const float*)d_in[21];
    const float* f1_w   = (const float*)d_in[22]; const float* f1_b   = (const float*)d_in[23];
    const float* f2_w   = (const float*)d_in[24]; const float* f2_b   = (const float*)d_in[25];
    const float* n3_g   = (const float*)d_in[26]; const float* n3_b   = (const float*)d_in[27];

    float *h, *q, *k, *v, *proj, *proj2, *ffn, *Ks, *Vs, *op, *ml, *mlw, *zb;
    cudaGetSymbolAddress((void**)&h,     g_h);
    cudaGetSymbolAddress((void**)&q,     g_q);
    cudaGetSymbolAddress((void**)&k,     g_k);
    cudaGetSymbolAddress((void**)&v,     g_v);
    cudaGetSymbolAddress((void**)&proj,  g_proj);
    cudaGetSymbolAddress((void**)&proj2, g_proj2);
    cudaGetSymbolAddress((void**)&ffn,   g_ffn);
    cudaGetSymbolAddress((void**)&Ks,    g_Ks);
    cudaGetSymbolAddress((void**)&Vs,    g_Vs);
    cudaGetSymbolAddress((void**)&op,    g_op);
    cudaGetSymbolAddress((void**)&ml,    g_ml);
    cudaGetSymbolAddress((void**)&mlw,   g_mlw);
    cudaGetSymbolAddress((void**)&zb,    g_zb);

    cudaFuncSetAttribute((const void*)attn_mma,
                         cudaFuncAttributeMaxDynamicSharedMemorySize, ASMEM);
    cudaFuncSetAttribute((const void*)gemm_mma<0>,
                         cudaFuncAttributeMaxDynamicSharedMemorySize, GSMEM);
    cudaFuncSetAttribute((const void*)gemm_mma<1>,
                         cudaFuncAttributeMaxDynamicSharedMemorySize, GSMEM);

    const dim3 gP3(EE / 64, T2 / 128, 3);   // fused QKV
    const dim3 gP2(EE / 64, T2 / 128, 2);   // fused Ks/Vs, split-K O-proj & f2
    const dim3 gF (FF / 64, T2 / 128, 1);   // f1
    const dim3 gA (T2 / 128, NH, 2);        // attention split-KV
    const dim3 gW (NH * T2 / 256, 1, 1);    // mlw

    copyk<<<T2 * EE / 1024, 256>>>(x, h);
    gemm_mma<0><<<gP2, 256, GSMEM>>>(enc, nullptr,
        k_w, k_b, Ks, v_w, v_b, Vs, v_w, v_b, Vs, EE, EE, EE, 0, 0, 0);

    for (int l = 0; l < NL; l++) {
        const size_t wo = (size_t)l * EE * EE, bo = (size_t)l * EE;
        // self-attention: fused QKV projections
        gemm_mma<0><<<gP3, 256, GSMEM>>>(h, nullptr,
            sa_q_w + wo, sa_q_b + bo, q,
            sa_k_w + wo, sa_k_b + bo, k,
            sa_v_w + wo, sa_v_b + bo, v, EE, EE, EE, 0, 0, 0);
        attn_mma<<<gA, 128, ASMEM>>>(q, k, v, am, op, ml, T2, 1);
        mlw_kernel<<<gW, 256>>>(ml, mlw);
        // O-projection: split-K x2 with inline combine (relu deferred to LN)
        gemm_mma<1><<<gP2, 256, GSMEM>>>(op, mlw,
            sa_o_w + wo,                    sa_o_b + bo, proj,
            sa_o_w + wo + (size_t)256 * EE, zb,          proj2,
            sa_o_w + wo,                    sa_o_b + bo, proj,
            EE, EE, 256, 256, 4, 0);
        add_relu_ln<<<T2, 128>>>(h, proj, proj2, n1_g + bo, n1_b + bo, h, 1);
        // cross-attention (Q = h directly, per reference)
        attn_mma<<<gA, 128, ASMEM>>>(h, Ks, Vs, em, op, ml, T1, 0);
        mlw_kernel<<<gW, 256>>>(ml, mlw);
        gemm_mma<1><<<gP2, 256, GSMEM>>>(op, mlw,
            ca_o_w + wo,                    ca_o_b + bo, proj,
            ca_o_w + wo + (size_t)256 * EE, zb,          proj2,
            ca_o_w + wo,                    ca_o_b + bo, proj,
            EE, EE, 256, 256, 4, 0);
        add_relu_ln<<<T2, 128>>>(h, proj, proj2, n2_g + bo, n2_b + bo, h, 1);
        // FFN: f1 full-K, f2 split-K x2 (partials summed in add_relu_ln)
        gemm_mma<0><<<gF, 256, GSMEM>>>(h, nullptr,
            f1_w + (size_t)l * EE * FF, f1_b + (size_t)l * FF, ffn,
            f1_w + (size_t)l * EE * FF, f1_b + (size_t)l * FF, ffn,
            f1_w + (size_t)l * EE * FF, f1_b + (size_t)l * FF, ffn, FF, EE, EE, 0, 0, 1);
        gemm_mma<0><<<gP2, 256, GSMEM>>>(ffn, nullptr,
            f2_w + (size_t)l * FF * EE,                      f2_b + bo, proj,
            f2_w + (size_t)l * FF * EE + (size_t)1024 * EE,  zb,        proj2,
            f2_w + (size_t)l * FF * EE,                      f2_b + bo, proj,
            EE, FF, 1024, 1024, 0, 0);
        add_relu_ln<<<T2, 128>>>(h, proj, proj2, n3_g + bo, n3_b + bo, h, 0);
    }

    copyk<<<T2 * EE / 1024, 256>>>(h, (float*)d_out);
}

// round 11
// speedup vs baseline: 1.3976x; 1.2446x over previous
#include <cuda_runtime.h>
#include <cuda_fp16.h>
#include <cstdint>

#define T2 2048
#define T1 2048
#define EE 512
#define FF 2048
#define NL 4
#define NH 8
#define LOG2E 1.4426950408889634f

// ---------------- scratch (device globals; allocation-free) ----------------
__device__ float g_h    [T2*EE];
__device__ float g_q    [T2*EE];
__device__ float g_k    [T2*EE];
__device__ float g_v    [T2*EE];
__device__ float g_proj [T2*EE];
__device__ float g_proj2[T2*EE];
__device__ float g_ffn  [T2*FF];
__device__ float g_Ks   [T1*EE];
__device__ float g_Vs   [T1*EE];
__device__ float g_op   [2*T2*EE];      // split-KV partial O (unnormalized)
__device__ float g_ml   [2*NH*T2*2];    // split-KV per-row (m log2-dom, l)
__device__ float g_mlw  [2*NH*T2];      // combine weights w0', w1'
__device__ float g_zb   [FF];           // zero bias (zero-initialized)

// ---------------- helpers ----------------
__device__ __forceinline__ void hmma(float* d, const uint32_t* a, const uint32_t* b) {
    asm volatile(
        "mma.sync.aligned.m16n8k16.row.col.f32.f16.f16.f32 "
        "{%0,%1,%2,%3}, {%4,%5,%6,%7}, {%8,%9}, {%0,%1,%2,%3};"
        : "+f"(d[0]), "+f"(d[1]), "+f"(d[2]), "+f"(d[3])
        : "r"(a[0]), "r"(a[1]), "r"(a[2]), "r"(a[3]), "r"(b[0]), "r"(b[1]));
}
#define LDSM4(R, PTR) do {                                                     \
    uint32_t a_ = (uint32_t)__cvta_generic_to_shared(PTR);                     \
    asm volatile("ldmatrix.sync.aligned.m8n8.x4.shared.b16 {%0,%1,%2,%3}, [%4];" \
        : "=r"((R)[0]), "=r"((R)[1]), "=r"((R)[2]), "=r"((R)[3]) : "r"(a_));   \
} while (0)
#define LDSM4T(R, PTR) do {                                                    \
    uint32_t a_ = (uint32_t)__cvta_generic_to_shared(PTR);                     \
    asm volatile("ldmatrix.sync.aligned.m8n8.x4.trans.shared.b16 {%0,%1,%2,%3}, [%4];" \
        : "=r"((R)[0]), "=r"((R)[1]), "=r"((R)[2]), "=r"((R)[3]) : "r"(a_));   \
} while (0)

__device__ __forceinline__ float ex2(float x) {
    float y;
    asm("ex2.approx.f32 %0, %1;" : "=f"(y) : "f"(x));
    return y;
}
__device__ __forceinline__ uint32_t packh2(float x, float y) {
    __half2 h = __floats2half2_rn(x, y);
    return *reinterpret_cast<uint32_t*>(&h);
}
// 2-term fp16 split: (x,y) -> hi pair + lo pair; x ≈ hi + lo to ~2.4e-7 rel.
__device__ __forceinline__ void split2(float x, float y, uint32_t& hi, uint32_t& lo) {
    float hx = __half2float(__float2half_rn(x));
    float hy = __half2float(__float2half_rn(y));
    hi = packh2(hx, hy);
    lo = packh2(x - hx, y - hy);
}

// ---------------- elementwise copy ----------------
__global__ void copyk(const float* __restrict__ in, float* __restrict__ out) {
    size_t i = ((size_t)blockIdx.x * blockDim.x + threadIdx.x) * 4;
    *(float4*)(out + i) = *(const float4*)(in + i);
}

// ---------------- ml -> combine weights (m in log2 domain) ----------------
__global__ __launch_bounds__(256) void mlw_kernel(
    const float* __restrict__ ml, float* __restrict__ mlw)
{
    const int i = blockIdx.x * 256 + threadIdx.x;   // i = head*T2 + row
    float m0 = ml[i * 2 + 0];
    float l0 = ml[i * 2 + 1];
    float m1 = ml[(NH * T2 + i) * 2 + 0];
    float l1 = ml[(NH * T2 + i) * 2 + 1];
    float m = fmaxf(m0, m1);
    float w0 = ex2(m0 - m), w1 = ex2(m1 - m);
    float inv = 1.f / (l0 * w0 + l1 * w1);
    mlw[i] = w0 * inv;
    mlw[NH * T2 + i] = w1 * inv;
}

// ---------------- GEMM: C = act(A @ Bh + bias), tile 128x64 -----------------
// A kept exact via 2-term split (Ah+Al), B rounded to fp16 (error averages out
// over K with ~1/sqrt(K) cancellation). 2 MMAs per fragment pair.
// 256 threads, 8 warps (4x2), warp 32x32, BK=32, 2-stage register pipeline.
// CMB=1: A is split-KV partial base (op); combine with mlw during load.
// stage halves: Ah[128][40]@0 Al@5120 Bh[32][72]@10240; GST=12544.
#define GST 12544
#define GSMEM (2 * GST * 2)   // 50176 B

template<int CMB>
__global__ __launch_bounds__(256, 2) void gemm_mma(
    const float* __restrict__ A, const float* __restrict__ mlw,
    const float* __restrict__ B0, const float* __restrict__ b0, float* __restrict__ C0,
    const float* __restrict__ B1, const float* __restrict__ b1, float* __restrict__ C1,
    const float* __restrict__ B2, const float* __restrict__ b2, float* __restrict__ C2,
    int N, int lda, int kCnt, int aoffZ, int hoffZ, int act)
{
    extern __shared__ __half hsm[];
    const int z = blockIdx.z;
    const float* B    = (z == 0) ? B0 : ((z == 1) ? B1 : B2);
    const float* bias = (z == 0) ? b0 : ((z == 1) ? b1 : b2);
    float*       C    = (z == 0) ? C0 : ((z == 1) ? C1 : C2);
    const float* Az   = A + (size_t)z * aoffZ;
    const int headOff = z * hoffZ;

    const int tid = threadIdx.x;
    const int wid = tid >> 5, lane = tid & 31;
    const int g = lane >> 2, t = lane & 3;
    const int bm = blockIdx.y * 128, bn = blockIdx.x * 64;
    const int wm = (wid >> 1) * 32, wn = (wid & 1) * 32;

    float acc[2][4][4];
    #pragma unroll
    for (int mi = 0; mi < 2; mi++)
        #pragma unroll
        for (int nj = 0; nj < 4; nj++)
            #pragma unroll
            for (int r = 0; r < 4; r++) acc[mi][nj][r] = 0.f;

    const int NC = kCnt >> 5;
    float4 ra[4], rb[2];

    #define GLDG(c) do {                                                        \
        _Pragma("unroll")                                                       \
        for (int j_ = 0; j_ < 4; j_++) {                                        \
            int idx_ = tid + j_ * 256;                                          \
            int row_ = bm + (idx_ >> 3);                                        \
            int col_ = (c) * 32 + (idx_ & 7) * 4;                               \
            if (CMB) {                                                          \
                int head_ = ((c) >> 1) + headOff;                               \
                float w0_ = mlw[head_ * T2 + row_];                             \
                float w1_ = mlw[NH * T2 + head_ * T2 + row_];                   \
                float4 a0_ = *(const float4*)(Az + (size_t)row_ * EE + col_);   \
                float4 a1_ = *(const float4*)(Az + (size_t)T2 * EE              \
                                              + (size_t)row_ * EE + col_);      \
                ra[j_].x = a0_.x * w0_ + a1_.x * w1_;                           \
                ra[j_].y = a0_.y * w0_ + a1_.y * w1_;                           \
                ra[j_].z = a0_.z * w0_ + a1_.z * w1_;                           \
                ra[j_].w = a0_.w * w0_ + a1_.w * w1_;                           \
            } else {                                                            \
                ra[j_] = *(const float4*)(Az + (size_t)row_ * lda + col_);      \
            }                                                                   \
        }                                                                       \
        _Pragma("unroll")                                                       \
        for (int j_ = 0; j_ < 2; j_++) {                                        \
            int idx_ = tid + j_ * 256;                                          \
            rb[j_] = *(const float4*)(B + (size_t)((c) * 32 + (idx_ >> 4)) * N  \
                                      + bn + (idx_ & 15) * 4);                  \
        }                                                                       \
    } while (0)

    #define GSTS(s) do {                                                        \
        __half* st_ = hsm + (s) * GST;                                          \
        _Pragma("unroll")                                                       \
        for (int j_ = 0; j_ < 4; j_++) {                                        \
            int idx_ = tid + j_ * 256;                                          \
            int m_ = idx_ >> 3, kq_ = idx_ & 7;                                 \
            uint32_t h01, l01, h23, l23;                                        \
            split2(ra[j_].x, ra[j_].y, h01, l01);                               \
            split2(ra[j_].z, ra[j_].w, h23, l23);                               \
            *(uint2*)(st_ + m_ * 40 + kq_ * 4) = make_uint2(h01, h23);          \
            *(uint2*)(st_ + 5120 + m_ * 40 + kq_ * 4) = make_uint2(l01, l23);   \
        }                                                                       \
        _Pragma("unroll")                                                       \
        for (int j_ = 0; j_ < 2; j_++) {                                        \
            int idx_ = tid + j_ * 256;                                          \
            int k_ = idx_ >> 4, nq_ = idx_ & 15;                                \
            uint32_t h01 = packh2(rb[j_].x, rb[j_].y);                          \
            uint32_t h23 = packh2(rb[j_].z, rb[j_].w);                          \
            *(uint2*)(st_ + 10240 + k_ * 72 + nq_ * 4) = make_uint2(h01, h23);  \
        }                                                                       \
    } while (0)

    GLDG(0); GSTS(0);
    if (NC > 1) GLDG(1);
    __syncthreads();

    for (int c = 0; c < NC; c++) {
        if (c + 1 < NC) GSTS((c + 1) & 1);
        if (c + 2 < NC) GLDG(c + 2);

        __half* st = hsm + (c & 1) * GST;
        #pragma unroll
        for (int ks = 0; ks < 2; ks++) {
            const int kb = ks * 16;
            uint32_t Ahf[2][4], Alf[2][4], Bhf[2][4];
            const int arow = (lane & 15), acol = kb + (lane >> 4) * 8;
            #pragma unroll
            for (int mi = 0; mi < 2; mi++) {
                __half* ap = st + (wm + mi * 16 + arow) * 40 + acol;
                LDSM4(Ahf[mi], ap);
                LDSM4(Alf[mi], ap + 5120);
            }
            const int krow = kb + ((lane >> 3) & 1) * 8 + (lane & 7);
            #pragma unroll
            for (int nq = 0; nq < 2; nq++) {
                const int ncol = wn + nq * 16 + ((lane >> 4) & 1) * 8;
                __half* bp = st + 10240 + krow * 72 + ncol;
                LDSM4T(Bhf[nq], bp);
            }
            #pragma unroll
            for (int mi = 0; mi < 2; mi++)
                #pragma unroll
                for (int nj = 0; nj < 4; nj++) {
                    const uint32_t* bh = &Bhf[nj >> 1][(nj & 1) * 2];
                    hmma(acc[mi][nj], Ahf[mi], bh);
                    hmma(acc[mi][nj], Alf[mi], bh);
                }
        }
        __syncthreads();
    }

    #pragma unroll
    for (int mi = 0; mi < 2; mi++) {
        #pragma unroll
        for (int nj = 0; nj < 4; nj++) {
            const int row = bm + wm + mi * 16 + g;
            const int col = bn + wn + nj * 8 + t * 2;
            float2 bv = *(const float2*)(bias + col);
            float2 w0, w1;
            w0.x = acc[mi][nj][0] + bv.x; w0.y = acc[mi][nj][1] + bv.y;
            w1.x = acc[mi][nj][2] + bv.x; w1.y = acc[mi][nj][3] + bv.y;
            if (act) {
                w0.x = fmaxf(w0.x, 0.f); w0.y = fmaxf(w0.y, 0.f);
                w1.x = fmaxf(w1.x, 0.f); w1.y = fmaxf(w1.y, 0.f);
            }
            *(float2*)(C + (size_t)row * N + col) = w0;
            *(float2*)(C + (size_t)(row + 8) * N + col) = w1;
        }
    }
    #undef GLDG
    #undef GSTS
}

// ---------------- fp16 flash attention, split-KV x2 -------------------------
// Q kept exact (2-term split, pre-scaled by log2e); K and V rounded to fp16
// (errors average over Tk). S = (Qh+Ql)*Kh (2 MMA), PV = Ph*Vh (1 MMA).
// CTA: 128 q-rows x 1 head x 1 KV-half; 4 warps x 32 q-rows; KV chunks of 64.
// smem halves: Qh[128][72]@0 Ql@9216 Kh[64][72]@18432 Vh@23040; 55296 B.
#define ASMEM 55296

__global__ __launch_bounds__(128, 2) void attn_mma(
    const float* __restrict__ Q, const float* __restrict__ K,
    const float* __restrict__ V, const float* __restrict__ mask,
    float* __restrict__ Opart, float* __restrict__ ml,
    int Tk, int maskFull)
{
    extern __shared__ __half hsm[];
    __half* Qh = hsm;              // lo at +9216
    __half* Kh = hsm + 18432;
    __half* Vh = hsm + 23040;

    const int tid = threadIdx.x;
    const int wid = tid >> 5, lane = tid & 31;
    const int g = lane >> 2, t = lane & 3;
    const int q0 = blockIdx.x * 128, hc = blockIdx.y * 64;
    const int s = blockIdx.z;
    const int kbase = s * (Tk >> 1);
    const int wm = wid * 32;
    float* op = Opart + (size_t)s * T2 * EE;

    // Q tile 128x64 -> split fp16, pre-scaled by log2e
    #pragma unroll
    for (int j = 0; j < 16; j++) {
        int idx = tid + j * 128;
        int r = idx >> 4, dq = idx & 15;
        float4 qv = *(const float4*)(Q + (size_t)(q0 + r) * EE + hc + dq * 4);
        uint32_t h01, l01, h23, l23;
        split2(qv.x * LOG2E, qv.y * LOG2E, h01, l01);
        split2(qv.z * LOG2E, qv.w * LOG2E, h23, l23);
        *(uint2*)(Qh + r * 72 + dq * 4) = make_uint2(h01, h23);
        *(uint2*)(Qh + 9216 + r * 72 + dq * 4) = make_uint2(l01, l23);
    }

    // shared K/V staging registers (disjoint lifetimes)
    float4 rkv[8];
    #pragma unroll
    for (int j = 0; j < 8; j++) {
        int idx = tid + j * 128;
        rkv[j] = *(const float4*)(K + (size_t)(kbase + (idx >> 4)) * EE + hc + (idx & 15) * 4);
    }

    float m_run[4], l_run[4];
    #pragma unroll
    for (int r = 0; r < 4; r++) { m_run[r] = -1e30f; l_run[r] = 0.f; }
    float oacc[2][8][4];
    #pragma unroll
    for (int mi = 0; mi < 2; mi++)
        #pragma unroll
        for (int nj = 0; nj < 8; nj++)
            #pragma unroll
            for (int r = 0; r < 4; r++) oacc[mi][nj][r] = 0.f;

    const int NCH = Tk >> 7;    // chunks of 64 within this half
    for (int c = 0; c < NCH; c++) {
        const int kr0 = kbase + c * 64;

        // ---- STS K (fp16) from rkv ----
        #pragma unroll
        for (int j = 0; j < 8; j++) {
            int idx = tid + j * 128;
            int kr = idx >> 4, dq = idx & 15;
            *(uint2*)(Kh + kr * 72 + dq * 4) =
                make_uint2(packh2(rkv[j].x, rkv[j].y), packh2(rkv[j].z, rkv[j].w));
        }
        __syncthreads();   // K (and Q on c=0) ready; all warps past PV(c-1)

        // ---- LDG V chunk c (latency hidden by S-MMA) ----
        #pragma unroll
        for (int j = 0; j < 8; j++) {
            int idx = tid + j * 128;
            rkv[j] = *(const float4*)(V + (size_t)(kr0 + (idx >> 4)) * EE + hc + (idx & 15) * 4);
        }

        // ---- S = Q @ K^T (log2 domain; Q exact, K fp16) ----
        float sreg[2][8][4];
        #pragma unroll
        for (int mi = 0; mi < 2; mi++)
            #pragma unroll
            for (int nj = 0; nj < 8; nj++)
                #pragma unroll
                for (int r = 0; r < 4; r++) sreg[mi][nj][r] = 0.f;

        #pragma unroll
        for (int ks = 0; ks < 4; ks++) {
            uint32_t qh[2][4], ql[2][4];
            #pragma unroll
            for (int mi = 0; mi < 2; mi++) {
                __half* qp = Qh + (wm + mi * 16 + (lane & 15)) * 72 + ks * 16 + (lane >> 4) * 8;
                LDSM4(qh[mi], qp);
                LDSM4(ql[mi], qp + 9216);
            }
            const int kvrow = ((lane >> 4) & 1) * 8 + (lane & 7);
            const int dcol = ks * 16 + ((lane >> 3) & 1) * 8;
            #pragma unroll
            for (int nq = 0; nq < 4; nq++) {
                uint32_t kh4[4];
                __half* kp = Kh + (nq * 16 + kvrow) * 72 + dcol;
                LDSM4(kh4, kp);
                #pragma unroll
                for (int mi = 0; mi < 2; mi++)
                    #pragma unroll
                    for (int hb = 0; hb < 2; hb++) {
                        float* sd = sreg[mi][nq * 2 + hb];
                        const uint32_t* bh = kh4 + hb * 2;
                        hmma(sd, qh[mi], bh);
                        hmma(sd, ql[mi], bh);
                    }
            }
        }

        // ---- mask add (scaled into log2 domain) ----
        if (maskFull) {
            #pragma unroll
            for (int mi = 0; mi < 2; mi++) {
                const int row0 = q0 + wm + mi * 16 + g;
                #pragma unroll
                for (int nj = 0; nj < 8; nj++) {
                    float2 m0 = *(const float2*)(mask + (size_t)row0 * Tk + kr0 + nj * 8 + t * 2);
                    float2 m1 = *(const float2*)(mask + (size_t)(row0 + 8) * Tk + kr0 + nj * 8 + t * 2);
                    sreg[mi][nj][0] = fmaf(m0.x, LOG2E, sreg[mi][nj][0]);
                    sreg[mi][nj][1] = fmaf(m0.y, LOG2E, sreg[mi][nj][1]);
                    sreg[mi][nj][2] = fmaf(m1.x, LOG2E, sreg[mi][nj][2]);
                    sreg[mi][nj][3] = fmaf(m1.y, LOG2E, sreg[mi][nj][3]);
                }
            }
        } else {
            #pragma unroll
            for (int nj = 0; nj < 8; nj++) {
                float2 mv = *(const float2*)(mask + kr0 + nj * 8 + t * 2);
                #pragma unroll
                for (int mi = 0; mi < 2; mi++) {
                    sreg[mi][nj][0] = fmaf(mv.x, LOG2E, sreg[mi][nj][0]);
                    sreg[mi][nj][1] = fmaf(mv.y, LOG2E, sreg[mi][nj][1]);
                    sreg[mi][nj][2] = fmaf(mv.x, LOG2E, sreg[mi][nj][2]);
                    sreg[mi][nj][3] = fmaf(mv.y, LOG2E, sreg[mi][nj][3]);
                }
            }
        }

        // ---- online softmax in log2 domain (4 row-slots: mi*2 + rr) ----
        #pragma unroll
        for (int mi = 0; mi < 2; mi++)
            #pragma unroll
            for (int rr = 0; rr < 2; rr++) {
                const int r = mi * 2 + rr;
                float tm = -1e30f;
                #pragma unroll
                for (int nj = 0; nj < 8; nj++)
                    tm = fmaxf(tm, fmaxf(sreg[mi][nj][rr * 2], sreg[mi][nj][rr * 2 + 1]));
                tm = fmaxf(tm, __shfl_xor_sync(0xffffffffu, tm, 1));
                tm = fmaxf(tm, __shfl_xor_sync(0xffffffffu, tm, 2));
                float nm = fmaxf(m_run[r], tm);
                float sc = ex2(m_run[r] - nm);
                float rs = 0.f;
                #pragma unroll
                for (int nj = 0; nj < 8; nj++) {
                    float p0 = ex2(sreg[mi][nj][rr * 2] - nm);
                    float p1 = ex2(sreg[mi][nj][rr * 2 + 1] - nm);
                    sreg[mi][nj][rr * 2] = p0; sreg[mi][nj][rr * 2 + 1] = p1;
                    rs += p0 + p1;
                }
                rs += __shfl_xor_sync(0xffffffffu, rs, 1);
                rs += __shfl_xor_sync(0xffffffffu, rs, 2);
                l_run[r] = l_run[r] * sc + rs;
                m_run[r] = nm;
                #pragma unroll
                for (int nj = 0; nj < 8; nj++) {
                    oacc[mi][nj][rr * 2] *= sc;
                    oacc[mi][nj][rr * 2 + 1] *= sc;
                }
            }

        // ---- STS V (fp16) from rkv ----
        #pragma unroll
        for (int j = 0; j < 8; j++) {
            int idx = tid + j * 128;
            int kr = idx >> 4, dq = idx & 15;
            *(uint2*)(Vh + kr * 72 + dq * 4) =
                make_uint2(packh2(rkv[j].x, rkv[j].y), packh2(rkv[j].z, rkv[j].w));
        }
        __syncthreads();   // V ready; all warps past S(c)

        // ---- LDG K chunk c+1 (latency hidden by PV) ----
        if (c + 1 < NCH) {
            const int kn0 = kbase + (c + 1) * 64;
            #pragma unroll
            for (int j = 0; j < 8; j++) {
                int idx = tid + j * 128;
                rkv[j] = *(const float4*)(K + (size_t)(kn0 + (idx >> 4)) * EE + hc + (idx & 15) * 4);
            }
        }

        // ---- O += P @ V (P fp16, V fp16: 1 MMA) ----
        #pragma unroll
        for (int ks = 0; ks < 4; ks++) {
            uint32_t ph[2][4];
            #pragma unroll
            for (int mi = 0; mi < 2; mi++) {
                ph[mi][0] = packh2(sreg[mi][2 * ks][0],     sreg[mi][2 * ks][1]);
                ph[mi][1] = packh2(sreg[mi][2 * ks][2],     sreg[mi][2 * ks][3]);
                ph[mi][2] = packh2(sreg[mi][2 * ks + 1][0], sreg[mi][2 * ks + 1][1]);
                ph[mi][3] = packh2(sreg[mi][2 * ks + 1][2], sreg[mi][2 * ks + 1][3]);
            }
            const int krow = ks * 16 + ((lane >> 3) & 1) * 8 + (lane & 7);
            const int nc0 = ((lane >> 4) & 1) * 8;
            #pragma unroll
            for (int nq = 0; nq < 4; nq++) {
                uint32_t vh4[4];
                __half* vp = Vh + krow * 72 + nq * 16 + nc0;
                LDSM4T(vh4, vp);
                #pragma unroll
                for (int mi = 0; mi < 2; mi++)
                    #pragma unroll
                    for (int hb = 0; hb < 2; hb++)
                        hmma(oacc[mi][nq * 2 + hb], ph[mi], vh4 + hb * 2);
            }
        }
    }

    // epilogue: unnormalized partials + (m, l)
    #pragma unroll
    for (int mi = 0; mi < 2; mi++) {
        const int row = q0 + wm + mi * 16 + g;
        #pragma unroll
        for (int nj = 0; nj < 8; nj++) {
            const int col = hc + nj * 8 + t * 2;
            *(float2*)(op + (size_t)row * EE + col) =
                make_float2(oacc[mi][nj][0], oacc[mi][nj][1]);
            *(float2*)(op + (size_t)(row + 8) * EE + col) =
                make_float2(oacc[mi][nj][2], oacc[mi][nj][3]);
        }
        if (t == 0) {
            const size_t base = ((size_t)s * NH + blockIdx.y) * T2;
            ml[(base + row) * 2 + 0] = m_run[mi * 2];
            ml[(base + row) * 2 + 1] = l_run[mi * 2];
            ml[(base + row + 8) * 2 + 0] = m_run[mi * 2 + 1];
            ml[(base + row + 8) * 2 + 1] = l_run[mi * 2 + 1];
        }
    }
}

// ---------------- out = LN(relu(h + f(a [+ a2]))) * g + b -------------------
// innerRelu=1: f = relu (for split-K O-projections); else f = identity.
__global__ __launch_bounds__(128) void add_relu_ln(
    const float* __restrict__ h, const float* __restrict__ a,
    const float* __restrict__ a2,
    const float* __restrict__ g, const float* __restrict__ b,
    float* __restrict__ out, int innerRelu)
{
    __shared__ float red[4];
    const int row = blockIdx.x;
    const int tid = threadIdx.x;
    const int c = tid * 4;

    float4 hv = *(const float4*)(h + (size_t)row * EE + c);
    float4 av = *(const float4*)(a + (size_t)row * EE + c);
    if (a2) {
        float4 a2v = *(const float4*)(a2 + (size_t)row * EE + c);
        av.x += a2v.x; av.y += a2v.y; av.z += a2v.z; av.w += a2v.w;
    }
    if (innerRelu) {
        av.x = fmaxf(av.x, 0.f); av.y = fmaxf(av.y, 0.f);
        av.z = fmaxf(av.z, 0.f); av.w = fmaxf(av.w, 0.f);
    }
    float v[4] = { fmaxf(hv.x + av.x, 0.f), fmaxf(hv.y + av.y, 0.f),
                   fmaxf(hv.z + av.z, 0.f), fmaxf(hv.w + av.w, 0.f) };

    float s = v[0] + v[1] + v[2] + v[3];
    #pragma unroll
    for (int m = 16; m; m >>= 1) s += __shfl_xor_sync(0xffffffffu, s, m);
    if ((tid & 31) == 0) red[tid >> 5] = s;
    __syncthreads();
    float mean = (red[0] + red[1] + red[2] + red[3]) * (1.f / EE);
    __syncthreads();

    float d = 0.f;
    #pragma unroll
    for (int j = 0; j < 4; j++) { float tt = v[j] - mean; d += tt * tt; }
    #pragma unroll
    for (int m = 16; m; m >>= 1) d += __shfl_xor_sync(0xffffffffu, d, m);
    if ((tid & 31) == 0) red[tid >> 5] = d;
    __syncthreads();
    float var = (red[0] + red[1] + red[2] + red[3]) * (1.f / EE);
    float rstd = rsqrtf(var + 1e-5f);

    float4 gv = *(const float4*)(g + c);
    float4 bv = *(const float4*)(b + c);
    float4 w = make_float4((v[0] - mean) * rstd * gv.x + bv.x,
                           (v[1] - mean) * rstd * gv.y + bv.y,
                           (v[2] - mean) * rstd * gv.z + bv.z,
                           (v[3] - mean) * rstd * gv.w + bv.w);
    *(float4*)(out + (size_t)row * EE + c) = w;
}

// ---------------- launch ----------------
extern "C" void kernel_launch(void* const* d_in, const int* in_sizes, int n_in,
                              void* d_out, int out_size)
{
    (void)in_sizes; (void)n_in; (void)out_size;
    const float* x      = (const float*)d_in[0];
    const float* enc    = (const float*)d_in[1];
    const float* am     = (const float*)d_in[2];
    const float* em     = (const float*)d_in[3];
    const float* k_w    = (const float*)d_in[4];
    const float* k_b    = (const float*)d_in[5];
    const float* v_w    = (const float*)d_in[6];
    const float* v_b    = (const float*)d_in[7];
    const float* sa_q_w = (const float*)d_in[8];  const float* sa_q_b = (const float*)d_in[9];
    const float* sa_k_w = (const float*)d_in[10]; const float* sa_k_b = (const float*)d_in[11];
    const float* sa_v_w = (const float*)d_in[12]; const float* sa_v_b = (const float*)d_in[13];
    const float* sa_o_w = (const float*)d_in[14]; const float* sa_o_b = (const float*)d_in[15];
    const float* n1_g   = (const float*)d_in[16]; const float* n1_b   = (const float*)d_in[17];
    const float* ca_o_w = (const float*)d_in[18]; const float* ca_o_b = (const float*)d_in[19];
    const float* n2_g   = (const float*)d_in[20]; const float* n2_b   = (const float*)d_in[21];
    const float* f1_w   = (const float*)d_in[22]; const float* f1_b   = (const float*)d_in[23];
    const float* f2_w   = (const float*)d_in[24]; const float* f2_b   = (const float*)d_in[25];
    const float* n3_g   = (const float*)d_in[26]; const float* n3_b   = (const float*)d_in[27];

    float *h, *q, *k, *v, *proj, *proj2, *ffn, *Ks, *Vs, *op, *ml, *mlw, *zb;
    cudaGetSymbolAddress((void**)&h,     g_h);
    cudaGetSymbolAddress((void**)&q,     g_q);
    cudaGetSymbolAddress((void**)&k,     g_k);
    cudaGetSymbolAddress((void**)&v,     g_v);
    cudaGetSymbolAddress((void**)&proj,  g_proj);
    cudaGetSymbolAddress((void**)&proj2, g_proj2);
    cudaGetSymbolAddress((void**)&ffn,   g_ffn);
    cudaGetSymbolAddress((void**)&Ks,    g_Ks);
    cudaGetSymbolAddress((void**)&Vs,    g_Vs);
    cudaGetSymbolAddress((void**)&op,    g_op);
    cudaGetSymbolAddress((void**)&ml,    g_ml);
    cudaGetSymbolAddress((void**)&mlw,   g_mlw);
    cudaGetSymbolAddress((void**)&zb,    g_zb);

    cudaFuncSetAttribute((const void*)attn_mma,
                         cudaFuncAttributeMaxDynamicSharedMemorySize, ASMEM);
    cudaFuncSetAttribute((const void*)gemm_mma<0>,
                         cudaFuncAttributeMaxDynamicSharedMemorySize, GSMEM);
    cudaFuncSetAttribute((const void*)gemm_mma<1>,
                         cudaFuncAttributeMaxDynamicSharedMemorySize, GSMEM);

    const dim3 gP3(EE / 64, T2 / 128, 3);   // fused QKV
    const dim3 gP2(EE / 64, T2 / 128, 2);   // fused Ks/Vs, split-K O-proj & f2
    const dim3 gF (FF / 64, T2 / 128, 1);   // f1
    const dim3 gA (T2 / 128, NH, 2);        // attention split-KV
    const dim3 gW (NH * T2 / 256, 1, 1);    // mlw

    copyk<<<T2 * EE / 1024, 256>>>(x, h);
    gemm_mma<0><<<gP2, 256, GSMEM>>>(enc, nullptr,
        k_w, k_b, Ks, v_w, v_b, Vs, v_w, v_b, Vs, EE, EE, EE, 0, 0, 0);

    for (int l = 0; l < NL; l++) {
        const size_t wo = (size_t)l * EE * EE, bo = (size_t)l * EE;
        // self-attention: fused QKV projections
        gemm_mma<0><<<gP3, 256, GSMEM>>>(h, nullptr,
            sa_q_w + wo, sa_q_b + bo, q,
            sa_k_w + wo, sa_k_b + bo, k,
            sa_v_w + wo, sa_v_b + bo, v, EE, EE, EE, 0, 0, 0);
        attn_mma<<<gA, 128, ASMEM>>>(q, k, v, am, op, ml, T2, 1);
        mlw_kernel<<<gW, 256>>>(ml, mlw);
        // O-projection: split-K x2 with inline combine (relu deferred to LN)
        gemm_mma<1><<<gP2, 256, GSMEM>>>(op, mlw,
            sa_o_w + wo,                    sa_o_b + bo, proj,
            sa_o_w + wo + (size_t)256 * EE, zb,          proj2,
            sa_o_w + wo,                    sa_o_b + bo, proj,
            EE, EE, 256, 256, 4, 0);
        add_relu_ln<<<T2, 128>>>(h, proj, proj2, n1_g + bo, n1_b + bo, h, 1);
        // cross-attention (Q = h directly, per reference)
        attn_mma<<<gA, 128, ASMEM>>>(h, Ks, Vs, em, op, ml, T1, 0);
        mlw_kernel<<<gW, 256>>>(ml, mlw);
        gemm_mma<1><<<gP2, 256, GSMEM>>>(op, mlw,
            ca_o_w + wo,                    ca_o_b + bo, proj,
            ca_o_w + wo + (size_t)256 * EE, zb,          proj2,
            ca_o_w + wo,                    ca_o_b + bo, proj,
            EE, EE, 256, 256, 4, 0);
        add_relu_ln<<<T2, 128>>>(h, proj, proj2, n2_g + bo, n2_b + bo, h, 1);
        // FFN: f1 full-K, f2 split-K x2 (partials summed in add_relu_ln)
        gemm_mma<0><<<gF, 256, GSMEM>>>(h, nullptr,
            f1_w + (size_t)l * EE * FF, f1_b + (size_t)l * FF, ffn,
            f1_w + (size_t)l * EE * FF, f1_b + (size_t)l * FF, ffn,
            f1_w + (size_t)l * EE * FF, f1_b + (size_t)l * FF, ffn, FF, EE, EE, 0, 0, 1);
        gemm_mma<0><<<gP2, 256, GSMEM>>>(ffn, nullptr,
            f2_w + (size_t)l * FF * EE,                      f2_b + bo, proj,
            f2_w + (size_t)l * FF * EE + (size_t)1024 * EE,  zb,        proj2,
            f2_w + (size_t)l * FF * EE,                      f2_b + bo, proj,
            EE, FF, 1024, 1024, 0, 0);
        add_relu_ln<<<T2, 128>>>(h, proj, proj2, n3_g + bo, n3_b + bo, h, 0);
    }

    copyk<<<T2 * EE / 1024, 256>>>(h, (float*)d_out);
}

// round 12
// speedup vs baseline: 1.6751x; 1.1985x over previous
#include <cuda_runtime.h>
#include <cuda_fp16.h>
#include <cstdint>

#define T2 2048
#define T1 2048
#define EE 512
#define FF 2048
#define NL 4
#define NH 8
#define LOG2E 1.4426950408889634f

// ---------------- scratch (device globals; allocation-free) ----------------
__device__ float g_h    [T2*EE];
__device__ float g_q    [T2*EE];
__device__ float g_k    [T2*EE];
__device__ float g_v    [T2*EE];
__device__ float g_proj [T2*EE];
__device__ float g_proj2[T2*EE];
__device__ float g_ffn  [T2*FF];
__device__ float g_Ks   [T1*EE];
__device__ float g_Vs   [T1*EE];
__device__ float g_op   [2*T2*EE];      // split-KV partial O (unnormalized)
__device__ float g_ml   [2*NH*T2*2];    // split-KV per-row (m log2-dom, l)
__device__ float g_mlw  [2*NH*T2];      // combine weights w0', w1'
__device__ float g_zb   [FF];           // zero bias (zero-initialized)

// ---------------- helpers ----------------
__device__ __forceinline__ void hmma(float* d, const uint32_t* a, const uint32_t* b) {
    asm volatile(
        "mma.sync.aligned.m16n8k16.row.col.f32.f16.f16.f32 "
        "{%0,%1,%2,%3}, {%4,%5,%6,%7}, {%8,%9}, {%0,%1,%2,%3};"
        : "+f"(d[0]), "+f"(d[1]), "+f"(d[2]), "+f"(d[3])
        : "r"(a[0]), "r"(a[1]), "r"(a[2]), "r"(a[3]), "r"(b[0]), "r"(b[1]));
}
#define LDSM4(R, PTR) do {                                                     \
    uint32_t a_ = (uint32_t)__cvta_generic_to_shared(PTR);                     \
    asm volatile("ldmatrix.sync.aligned.m8n8.x4.shared.b16 {%0,%1,%2,%3}, [%4];" \
        : "=r"((R)[0]), "=r"((R)[1]), "=r"((R)[2]), "=r"((R)[3]) : "r"(a_));   \
} while (0)
#define LDSM4T(R, PTR) do {                                                    \
    uint32_t a_ = (uint32_t)__cvta_generic_to_shared(PTR);                     \
    asm volatile("ldmatrix.sync.aligned.m8n8.x4.trans.shared.b16 {%0,%1,%2,%3}, [%4];" \
        : "=r"((R)[0]), "=r"((R)[1]), "=r"((R)[2]), "=r"((R)[3]) : "r"(a_));   \
} while (0)

__device__ __forceinline__ float ex2(float x) {
    float y;
    asm("ex2.approx.f32 %0, %1;" : "=f"(y) : "f"(x));
    return y;
}
__device__ __forceinline__ uint32_t packh2(float x, float y) {
    __half2 h = __floats2half2_rn(x, y);
    return *reinterpret_cast<uint32_t*>(&h);
}

// ---------------- elementwise copy ----------------
__global__ void copyk(const float* __restrict__ in, float* __restrict__ out) {
    size_t i = ((size_t)blockIdx.x * blockDim.x + threadIdx.x) * 4;
    *(float4*)(out + i) = *(const float4*)(in + i);
}

// ---------------- ml -> combine weights (m in log2 domain) ----------------
__global__ __launch_bounds__(256) void mlw_kernel(
    const float* __restrict__ ml, float* __restrict__ mlw)
{
    const int i = blockIdx.x * 256 + threadIdx.x;   // i = head*T2 + row
    float m0 = ml[i * 2 + 0];
    float l0 = ml[i * 2 + 1];
    float m1 = ml[(NH * T2 + i) * 2 + 0];
    float l1 = ml[(NH * T2 + i) * 2 + 1];
    float m = fmaxf(m0, m1);
    float w0 = ex2(m0 - m), w1 = ex2(m1 - m);
    float inv = 1.f / (l0 * w0 + l1 * w1);
    mlw[i] = w0 * inv;
    mlw[NH * T2 + i] = w1 * inv;
}

// ---------------- GEMM: C = act(A @ B + bias), pure fp16 x fp16 -------------
// Both operands rounded to fp16 (errors average over K with ~1/sqrt(K)
// cancellation). 1 MMA per fragment pair. Tile 128x64, 256 threads, 8 warps
// (4x2), warp 32x32, BK=32, 2-stage register pipeline.
// CMB=1: A is split-KV partial base (op); combine with mlw during load.
// stage halves: Ah[128][40]@0 Bh[32][72]@5120; GST=7424.
#define GST 7424
#define GSMEM (2 * GST * 2)   // 29696 B

template<int CMB>
__global__ __launch_bounds__(256, 3) void gemm_mma(
    const float* __restrict__ A, const float* __restrict__ mlw,
    const float* __restrict__ B0, const float* __restrict__ b0, float* __restrict__ C0,
    const float* __restrict__ B1, const float* __restrict__ b1, float* __restrict__ C1,
    const float* __restrict__ B2, const float* __restrict__ b2, float* __restrict__ C2,
    int N, int lda, int kCnt, int aoffZ, int hoffZ, int act)
{
    extern __shared__ __half hsm[];
    const int z = blockIdx.z;
    const float* B    = (z == 0) ? B0 : ((z == 1) ? B1 : B2);
    const float* bias = (z == 0) ? b0 : ((z == 1) ? b1 : b2);
    float*       C    = (z == 0) ? C0 : ((z == 1) ? C1 : C2);
    const float* Az   = A + (size_t)z * aoffZ;
    const int headOff = z * hoffZ;

    const int tid = threadIdx.x;
    const int wid = tid >> 5, lane = tid & 31;
    const int g = lane >> 2, t = lane & 3;
    const int bm = blockIdx.y * 128, bn = blockIdx.x * 64;
    const int wm = (wid >> 1) * 32, wn = (wid & 1) * 32;

    float acc[2][4][4];
    #pragma unroll
    for (int mi = 0; mi < 2; mi++)
        #pragma unroll
        for (int nj = 0; nj < 4; nj++)
            #pragma unroll
            for (int r = 0; r < 4; r++) acc[mi][nj][r] = 0.f;

    const int NC = kCnt >> 5;
    float4 ra[4], rb[2];

    #define GLDG(c) do {                                                        \
        _Pragma("unroll")                                                       \
        for (int j_ = 0; j_ < 4; j_++) {                                        \
            int idx_ = tid + j_ * 256;                                          \
            int row_ = bm + (idx_ >> 3);                                        \
            int col_ = (c) * 32 + (idx_ & 7) * 4;                               \
            if (CMB) {                                                          \
                int head_ = ((c) >> 1) + headOff;                               \
                float w0_ = mlw[head_ * T2 + row_];                             \
                float w1_ = mlw[NH * T2 + head_ * T2 + row_];                   \
                float4 a0_ = *(const float4*)(Az + (size_t)row_ * EE + col_);   \
                float4 a1_ = *(const float4*)(Az + (size_t)T2 * EE              \
                                              + (size_t)row_ * EE + col_);      \
                ra[j_].x = a0_.x * w0_ + a1_.x * w1_;                           \
                ra[j_].y = a0_.y * w0_ + a1_.y * w1_;                           \
                ra[j_].z = a0_.z * w0_ + a1_.z * w1_;                           \
                ra[j_].w = a0_.w * w0_ + a1_.w * w1_;                           \
            } else {                                                            \
                ra[j_] = *(const float4*)(Az + (size_t)row_ * lda + col_);      \
            }                                                                   \
        }                                                                       \
        _Pragma("unroll")                                                       \
        for (int j_ = 0; j_ < 2; j_++) {                                        \
            int idx_ = tid + j_ * 256;                                          \
            rb[j_] = *(const float4*)(B + (size_t)((c) * 32 + (idx_ >> 4)) * N  \
                                      + bn + (idx_ & 15) * 4);                  \
        }                                                                       \
    } while (0)

    #define GSTS(s) do {                                                        \
        __half* st_ = hsm + (s) * GST;                                          \
        _Pragma("unroll")                                                       \
        for (int j_ = 0; j_ < 4; j_++) {                                        \
            int idx_ = tid + j_ * 256;                                          \
            int m_ = idx_ >> 3, kq_ = idx_ & 7;                                 \
            *(uint2*)(st_ + m_ * 40 + kq_ * 4) =                                \
                make_uint2(packh2(ra[j_].x, ra[j_].y),                          \
                           packh2(ra[j_].z, ra[j_].w));                         \
        }                                                                       \
        _Pragma("unroll")                                                       \
        for (int j_ = 0; j_ < 2; j_++) {                                        \
            int idx_ = tid + j_ * 256;                                          \
            int k_ = idx_ >> 4, nq_ = idx_ & 15;                                \
            *(uint2*)(st_ + 5120 + k_ * 72 + nq_ * 4) =                         \
                make_uint2(packh2(rb[j_].x, rb[j_].y),                          \
                           packh2(rb[j_].z, rb[j_].w));                         \
        }                                                                       \
    } while (0)

    GLDG(0); GSTS(0);
    if (NC > 1) GLDG(1);
    __syncthreads();

    for (int c = 0; c < NC; c++) {
        if (c + 1 < NC) GSTS((c + 1) & 1);
        if (c + 2 < NC) GLDG(c + 2);

        __half* st = hsm + (c & 1) * GST;
        #pragma unroll
        for (int ks = 0; ks < 2; ks++) {
            const int kb = ks * 16;
            uint32_t Ahf[2][4], Bhf[2][4];
            const int arow = (lane & 15), acol = kb + (lane >> 4) * 8;
            #pragma unroll
            for (int mi = 0; mi < 2; mi++)
                LDSM4(Ahf[mi], st + (wm + mi * 16 + arow) * 40 + acol);
            const int krow = kb + ((lane >> 3) & 1) * 8 + (lane & 7);
            #pragma unroll
            for (int nq = 0; nq < 2; nq++) {
                const int ncol = wn + nq * 16 + ((lane >> 4) & 1) * 8;
                LDSM4T(Bhf[nq], st + 5120 + krow * 72 + ncol);
            }
            #pragma unroll
            for (int mi = 0; mi < 2; mi++)
                #pragma unroll
                for (int nj = 0; nj < 4; nj++)
                    hmma(acc[mi][nj], Ahf[mi], &Bhf[nj >> 1][(nj & 1) * 2]);
        }
        __syncthreads();
    }

    #pragma unroll
    for (int mi = 0; mi < 2; mi++) {
        #pragma unroll
        for (int nj = 0; nj < 4; nj++) {
            const int row = bm + wm + mi * 16 + g;
            const int col = bn + wn + nj * 8 + t * 2;
            float2 bv = *(const float2*)(bias + col);
            float2 w0, w1;
            w0.x = acc[mi][nj][0] + bv.x; w0.y = acc[mi][nj][1] + bv.y;
            w1.x = acc[mi][nj][2] + bv.x; w1.y = acc[mi][nj][3] + bv.y;
            if (act) {
                w0.x = fmaxf(w0.x, 0.f); w0.y = fmaxf(w0.y, 0.f);
                w1.x = fmaxf(w1.x, 0.f); w1.y = fmaxf(w1.y, 0.f);
            }
            *(float2*)(C + (size_t)row * N + col) = w0;
            *(float2*)(C + (size_t)(row + 8) * N + col) = w1;
        }
    }
    #undef GLDG
    #undef GSTS
}

// ---------------- fp16 flash attention, split-KV x2 -------------------------
// Q, K, V, P all fp16 (per-row logit offsets cancel in softmax; residual
// errors average over the Tk reduction). S = Qh*Kh (1 MMA), PV = Ph*Vh (1 MMA).
// log2-domain softmax (Q pre-scaled by log2e, ex2).
// CTA: 128 q-rows x 1 head x 1 KV-half; 4 warps x 32 q-rows; KV chunks of 64.
// smem halves: Qh[128][72]@0 Kh[64][72]@9216 Vh@13824; 36864 B.
#define ASMEM 36864

__global__ __launch_bounds__(128, 2) void attn_mma(
    const float* __restrict__ Q, const float* __restrict__ K,
    const float* __restrict__ V, const float* __restrict__ mask,
    float* __restrict__ Opart, float* __restrict__ ml,
    int Tk, int maskFull)
{
    extern __shared__ __half hsm[];
    __half* Qh = hsm;
    __half* Kh = hsm + 9216;
    __half* Vh = hsm + 13824;

    const int tid = threadIdx.x;
    const int wid = tid >> 5, lane = tid & 31;
    const int g = lane >> 2, t = lane & 3;
    const int q0 = blockIdx.x * 128, hc = blockIdx.y * 64;
    const int s = blockIdx.z;
    const int kbase = s * (Tk >> 1);
    const int wm = wid * 32;
    float* op = Opart + (size_t)s * T2 * EE;

    // Q tile 128x64 -> fp16, pre-scaled by log2e
    #pragma unroll
    for (int j = 0; j < 16; j++) {
        int idx = tid + j * 128;
        int r = idx >> 4, dq = idx & 15;
        float4 qv = *(const float4*)(Q + (size_t)(q0 + r) * EE + hc + dq * 4);
        *(uint2*)(Qh + r * 72 + dq * 4) =
            make_uint2(packh2(qv.x * LOG2E, qv.y * LOG2E),
                       packh2(qv.z * LOG2E, qv.w * LOG2E));
    }

    // shared K/V staging registers (disjoint lifetimes)
    float4 rkv[8];
    #pragma unroll
    for (int j = 0; j < 8; j++) {
        int idx = tid + j * 128;
        rkv[j] = *(const float4*)(K + (size_t)(kbase + (idx >> 4)) * EE + hc + (idx & 15) * 4);
    }

    float m_run[4], l_run[4];
    #pragma unroll
    for (int r = 0; r < 4; r++) { m_run[r] = -1e30f; l_run[r] = 0.f; }
    float oacc[2][8][4];
    #pragma unroll
    for (int mi = 0; mi < 2; mi++)
        #pragma unroll
        for (int nj = 0; nj < 8; nj++)
            #pragma unroll
            for (int r = 0; r < 4; r++) oacc[mi][nj][r] = 0.f;

    const int NCH = Tk >> 7;    // chunks of 64 within this half
    for (int c = 0; c < NCH; c++) {
        const int kr0 = kbase + c * 64;

        // ---- STS K (fp16) from rkv ----
        #pragma unroll
        for (int j = 0; j < 8; j++) {
            int idx = tid + j * 128;
            int kr = idx >> 4, dq = idx & 15;
            *(uint2*)(Kh + kr * 72 + dq * 4) =
                make_uint2(packh2(rkv[j].x, rkv[j].y), packh2(rkv[j].z, rkv[j].w));
        }
        __syncthreads();   // K (and Q on c=0) ready; all warps past PV(c-1)

        // ---- LDG V chunk c (latency hidden by S-MMA) ----
        #pragma unroll
        for (int j = 0; j < 8; j++) {
            int idx = tid + j * 128;
            rkv[j] = *(const float4*)(V + (size_t)(kr0 + (idx >> 4)) * EE + hc + (idx & 15) * 4);
        }

        // ---- S = Q @ K^T (log2 domain; 1 MMA) ----
        float sreg[2][8][4];
        #pragma unroll
        for (int mi = 0; mi < 2; mi++)
            #pragma unroll
            for (int nj = 0; nj < 8; nj++)
                #pragma unroll
                for (int r = 0; r < 4; r++) sreg[mi][nj][r] = 0.f;

        #pragma unroll
        for (int ks = 0; ks < 4; ks++) {
            uint32_t qh[2][4];
            #pragma unroll
            for (int mi = 0; mi < 2; mi++) {
                __half* qp = Qh + (wm + mi * 16 + (lane & 15)) * 72 + ks * 16 + (lane >> 4) * 8;
                LDSM4(qh[mi], qp);
            }
            const int kvrow = ((lane >> 4) & 1) * 8 + (lane & 7);
            const int dcol = ks * 16 + ((lane >> 3) & 1) * 8;
            #pragma unroll
            for (int nq = 0; nq < 4; nq++) {
                uint32_t kh4[4];
                LDSM4(kh4, Kh + (nq * 16 + kvrow) * 72 + dcol);
                #pragma unroll
                for (int mi = 0; mi < 2; mi++)
                    #pragma unroll
                    for (int hb = 0; hb < 2; hb++)
                        hmma(sreg[mi][nq * 2 + hb], qh[mi], kh4 + hb * 2);
            }
        }

        // ---- mask add (scaled into log2 domain) ----
        if (maskFull) {
            #pragma unroll
            for (int mi = 0; mi < 2; mi++) {
                const int row0 = q0 + wm + mi * 16 + g;
                #pragma unroll
                for (int nj = 0; nj < 8; nj++) {
                    float2 m0 = *(const float2*)(mask + (size_t)row0 * Tk + kr0 + nj * 8 + t * 2);
                    float2 m1 = *(const float2*)(mask + (size_t)(row0 + 8) * Tk + kr0 + nj * 8 + t * 2);
                    sreg[mi][nj][0] = fmaf(m0.x, LOG2E, sreg[mi][nj][0]);
                    sreg[mi][nj][1] = fmaf(m0.y, LOG2E, sreg[mi][nj][1]);
                    sreg[mi][nj][2] = fmaf(m1.x, LOG2E, sreg[mi][nj][2]);
                    sreg[mi][nj][3] = fmaf(m1.y, LOG2E, sreg[mi][nj][3]);
                }
            }
        } else {
            #pragma unroll
            for (int nj = 0; nj < 8; nj++) {
                float2 mv = *(const float2*)(mask + kr0 + nj * 8 + t * 2);
                #pragma unroll
                for (int mi = 0; mi < 2; mi++) {
                    sreg[mi][nj][0] = fmaf(mv.x, LOG2E, sreg[mi][nj][0]);
                    sreg[mi][nj][1] = fmaf(mv.y, LOG2E, sreg[mi][nj][1]);
                    sreg[mi][nj][2] = fmaf(mv.x, LOG2E, sreg[mi][nj][2]);
                    sreg[mi][nj][3] = fmaf(mv.y, LOG2E, sreg[mi][nj][3]);
                }
            }
        }

        // ---- online softmax in log2 domain (4 row-slots: mi*2 + rr) ----
        #pragma unroll
        for (int mi = 0; mi < 2; mi++)
            #pragma unroll
            for (int rr = 0; rr < 2; rr++) {
                const int r = mi * 2 + rr;
                float tm = -1e30f;
                #pragma unroll
                for (int nj = 0; nj < 8; nj++)
                    tm = fmaxf(tm, fmaxf(sreg[mi][nj][rr * 2], sreg[mi][nj][rr * 2 + 1]));
                tm = fmaxf(tm, __shfl_xor_sync(0xffffffffu, tm, 1));
                tm = fmaxf(tm, __shfl_xor_sync(0xffffffffu, tm, 2));
                float nm = fmaxf(m_run[r], tm);
                float sc = ex2(m_run[r] - nm);
                float rs = 0.f;
                #pragma unroll
                for (int nj = 0; nj < 8; nj++) {
                    float p0 = ex2(sreg[mi][nj][rr * 2] - nm);
                    float p1 = ex2(sreg[mi][nj][rr * 2 + 1] - nm);
                    sreg[mi][nj][rr * 2] = p0; sreg[mi][nj][rr * 2 + 1] = p1;
                    rs += p0 + p1;
                }
                rs += __shfl_xor_sync(0xffffffffu, rs, 1);
                rs += __shfl_xor_sync(0xffffffffu, rs, 2);
                l_run[r] = l_run[r] * sc + rs;
                m_run[r] = nm;
                #pragma unroll
                for (int nj = 0; nj < 8; nj++) {
                    oacc[mi][nj][rr * 2] *= sc;
                    oacc[mi][nj][rr * 2 + 1] *= sc;
                }
            }

        // ---- STS V (fp16) from rkv ----
        #pragma unroll
        for (int j = 0; j < 8; j++) {
            int idx = tid + j * 128;
            int kr = idx >> 4, dq = idx & 15;
            *(uint2*)(Vh + kr * 72 + dq * 4) =
                make_uint2(packh2(rkv[j].x, rkv[j].y), packh2(rkv[j].z, rkv[j].w));
        }
        __syncthreads();   // V ready; all warps past S(c)

        // ---- LDG K chunk c+1 (latency hidden by PV) ----
        if (c + 1 < NCH) {
            const int kn0 = kbase + (c + 1) * 64;
            #pragma unroll
            for (int j = 0; j < 8; j++) {
                int idx = tid + j * 128;
                rkv[j] = *(const float4*)(K + (size_t)(kn0 + (idx >> 4)) * EE + hc + (idx & 15) * 4);
            }
        }

        // ---- O += P @ V (1 MMA) ----
        #pragma unroll
        for (int ks = 0; ks < 4; ks++) {
            uint32_t ph[2][4];
            #pragma unroll
            for (int mi = 0; mi < 2; mi++) {
                ph[mi][0] = packh2(sreg[mi][2 * ks][0],     sreg[mi][2 * ks][1]);
                ph[mi][1] = packh2(sreg[mi][2 * ks][2],     sreg[mi][2 * ks][3]);
                ph[mi][2] = packh2(sreg[mi][2 * ks + 1][0], sreg[mi][2 * ks + 1][1]);
                ph[mi][3] = packh2(sreg[mi][2 * ks + 1][2], sreg[mi][2 * ks + 1][3]);
            }
            const int krow = ks * 16 + ((lane >> 3) & 1) * 8 + (lane & 7);
            const int nc0 = ((lane >> 4) & 1) * 8;
            #pragma unroll
            for (int nq = 0; nq < 4; nq++) {
                uint32_t vh4[4];
                LDSM4T(vh4, Vh + krow * 72 + nq * 16 + nc0);
                #pragma unroll
                for (int mi = 0; mi < 2; mi++)
                    #pragma unroll
                    for (int hb = 0; hb < 2; hb++)
                        hmma(oacc[mi][nq * 2 + hb], ph[mi], vh4 + hb * 2);
            }
        }
    }

    // epilogue: unnormalized partials + (m, l)
    #pragma unroll
    for (int mi = 0; mi < 2; mi++) {
        const int row = q0 + wm + mi * 16 + g;
        #pragma unroll
        for (int nj = 0; nj < 8; nj++) {
            const int col = hc + nj * 8 + t * 2;
            *(float2*)(op + (size_t)row * EE + col) =
                make_float2(oacc[mi][nj][0], oacc[mi][nj][1]);
            *(float2*)(op + (size_t)(row + 8) * EE + col) =
                make_float2(oacc[mi][nj][2], oacc[mi][nj][3]);
        }
        if (t == 0) {
            const size_t base = ((size_t)s * NH + blockIdx.y) * T2;
            ml[(base + row) * 2 + 0] = m_run[mi * 2];
            ml[(base + row) * 2 + 1] = l_run[mi * 2];
            ml[(base + row + 8) * 2 + 0] = m_run[mi * 2 + 1];
            ml[(base + row + 8) * 2 + 1] = l_run[mi * 2 + 1];
        }
    }
}

// ---------------- out = LN(relu(h + f(a [+ a2]))) * g + b -------------------
// innerRelu=1: f = relu (for split-K O-projections); else f = identity.
__global__ __launch_bounds__(128) void add_relu_ln(
    const float* __restrict__ h, const float* __restrict__ a,
    const float* __restrict__ a2,
    const float* __restrict__ g, const float* __restrict__ b,
    float* __restrict__ out, int innerRelu)
{
    __shared__ float red[4];
    const int row = blockIdx.x;
    const int tid = threadIdx.x;
    const int c = tid * 4;

    float4 hv = *(const float4*)(h + (size_t)row * EE + c);
    float4 av = *(const float4*)(a + (size_t)row * EE + c);
    if (a2) {
        float4 a2v = *(const float4*)(a2 + (size_t)row * EE + c);
        av.x += a2v.x; av.y += a2v.y; av.z += a2v.z; av.w += a2v.w;
    }
    if (innerRelu) {
        av.x = fmaxf(av.x, 0.f); av.y = fmaxf(av.y, 0.f);
        av.z = fmaxf(av.z, 0.f); av.w = fmaxf(av.w, 0.f);
    }
    float v[4] = { fmaxf(hv.x + av.x, 0.f), fmaxf(hv.y + av.y, 0.f),
                   fmaxf(hv.z + av.z, 0.f), fmaxf(hv.w + av.w, 0.f) };

    float s = v[0] + v[1] + v[2] + v[3];
    #pragma unroll
    for (int m = 16; m; m >>= 1) s += __shfl_xor_sync(0xffffffffu, s, m);
    if ((tid & 31) == 0) red[tid >> 5] = s;
    __syncthreads();
    float mean = (red[0] + red[1] + red[2] + red[3]) * (1.f / EE);
    __syncthreads();

    float d = 0.f;
    #pragma unroll
    for (int j = 0; j < 4; j++) { float tt = v[j] - mean; d += tt * tt; }
    #pragma unroll
    for (int m = 16; m; m >>= 1) d += __shfl_xor_sync(0xffffffffu, d, m);
    if ((tid & 31) == 0) red[tid >> 5] = d;
    __syncthreads();
    float var = (red[0] + red[1] + red[2] + red[3]) * (1.f / EE);
    float rstd = rsqrtf(var + 1e-5f);

    float4 gv = *(const float4*)(g + c);
    float4 bv = *(const float4*)(b + c);
    float4 w = make_float4((v[0] - mean) * rstd * gv.x + bv.x,
                           (v[1] - mean) * rstd * gv.y + bv.y,
                           (v[2] - mean) * rstd * gv.z + bv.z,
                           (v[3] - mean) * rstd * gv.w + bv.w);
    *(float4*)(out + (size_t)row * EE + c) = w;
}

// ---------------- launch ----------------
extern "C" void kernel_launch(void* const* d_in, const int* in_sizes, int n_in,
                              void* d_out, int out_size)
{
    (void)in_sizes; (void)n_in; (void)out_size;
    const float* x      = (const float*)d_in[0];
    const float* enc    = (const float*)d_in[1];
    const float* am     = (const float*)d_in[2];
    const float* em     = (const float*)d_in[3];
    const float* k_w    = (const float*)d_in[4];
    const float* k_b    = (const float*)d_in[5];
    const float* v_w    = (const float*)d_in[6];
    const float* v_b    = (const float*)d_in[7];
    const float* sa_q_w = (const float*)d_in[8];  const float* sa_q_b = (const float*)d_in[9];
    const float* sa_k_w = (const float*)d_in[10]; const float* sa_k_b = (const float*)d_in[11];
    const float* sa_v_w = (const float*)d_in[12]; const float* sa_v_b = (const float*)d_in[13];
    const float* sa_o_w = (const float*)d_in[14]; const float* sa_o_b = (const float*)d_in[15];
    const float* n1_g   = (const float*)d_in[16]; const float* n1_b   = (const float*)d_in[17];
    const float* ca_o_w = (const float*)d_in[18]; const float* ca_o_b = (const float*)d_in[19];
    const float* n2_g   = (const float*)d_in[20]; const float* n2_b   = (const float*)d_in[21];
    const float* f1_w   = (const float*)d_in[22]; const float* f1_b   = (const float*)d_in[23];
    const float* f2_w   = (const float*)d_in[24]; const float* f2_b   = (const float*)d_in[25];
    const float* n3_g   = (const float*)d_in[26]; const float* n3_b   = (const float*)d_in[27];

    float *h, *q, *k, *v, *proj, *proj2, *ffn, *Ks, *Vs, *op, *ml, *mlw, *zb;
    cudaGetSymbolAddress((void**)&h,     g_h);
    cudaGetSymbolAddress((void**)&q,     g_q);
    cudaGetSymbolAddress((void**)&k,     g_k);
    cudaGetSymbolAddress((void**)&v,     g_v);
    cudaGetSymbolAddress((void**)&proj,  g_proj);
    cudaGetSymbolAddress((void**)&proj2, g_proj2);
    cudaGetSymbolAddress((void**)&ffn,   g_ffn);
    cudaGetSymbolAddress((void**)&Ks,    g_Ks);
    cudaGetSymbolAddress((void**)&Vs,    g_Vs);
    cudaGetSymbolAddress((void**)&op,    g_op);
    cudaGetSymbolAddress((void**)&ml,    g_ml);
    cudaGetSymbolAddress((void**)&mlw,   g_mlw);
    cudaGetSymbolAddress((void**)&zb,    g_zb);

    cudaFuncSetAttribute((const void*)attn_mma,
                         cudaFuncAttributeMaxDynamicSharedMemorySize, ASMEM);
    cudaFuncSetAttribute((const void*)gemm_mma<0>,
                         cudaFuncAttributeMaxDynamicSharedMemorySize, GSMEM);
    cudaFuncSetAttribute((const void*)gemm_mma<1>,
                         cudaFuncAttributeMaxDynamicSharedMemorySize, GSMEM);

    const dim3 gP3(EE / 64, T2 / 128, 3);   // fused QKV
    const dim3 gP2(EE / 64, T2 / 128, 2);   // fused Ks/Vs, split-K O-proj & f2
    const dim3 gF (FF / 64, T2 / 128, 1);   // f1
    const dim3 gA (T2 / 128, NH, 2);        // attention split-KV
    const dim3 gW (NH * T2 / 256, 1, 1);    // mlw

    copyk<<<T2 * EE / 1024, 256>>>(x, h);
    gemm_mma<0><<<gP2, 256, GSMEM>>>(enc, nullptr,
        k_w, k_b, Ks, v_w, v_b, Vs, v_w, v_b, Vs, EE, EE, EE, 0, 0, 0);

    for (int l = 0; l < NL; l++) {
        const size_t wo = (size_t)l * EE * EE, bo = (size_t)l * EE;
        // self-attention: fused QKV projections
        gemm_mma<0><<<gP3, 256, GSMEM>>>(h, nullptr,
            sa_q_w + wo, sa_q_b + bo, q,
            sa_k_w + wo, sa_k_b + bo, k,
            sa_v_w + wo, sa_v_b + bo, v, EE, EE, EE, 0, 0, 0);
        attn_mma<<<gA, 128, ASMEM>>>(q, k, v, am, op, ml, T2, 1);
        mlw_kernel<<<gW, 256>>>(ml, mlw);
        // O-projection: split-K x2 with inline combine (relu deferred to LN)
        gemm_mma<1><<<gP2, 256, GSMEM>>>(op, mlw,
            sa_o_w + wo,                    sa_o_b + bo, proj,
            sa_o_w + wo + (size_t)256 * EE, zb,          proj2,
            sa_o_w + wo,                    sa_o_b + bo, proj,
            EE, EE, 256, 256, 4, 0);
        add_relu_ln<<<T2, 128>>>(h, proj, proj2, n1_g + bo, n1_b + bo, h, 1);
        // cross-attention (Q = h directly, per reference)
        attn_mma<<<gA, 128, ASMEM>>>(h, Ks, Vs, em, op, ml, T1, 0);
        mlw_kernel<<<gW, 256>>>(ml, mlw);
        gemm_mma<1><<<gP2, 256, GSMEM>>>(op, mlw,
            ca_o_w + wo,                    ca_o_b + bo, proj,
            ca_o_w + wo + (size_t)256 * EE, zb,          proj2,
            ca_o_w + wo,                    ca_o_b + bo, proj,
            EE, EE, 256, 256, 4, 0);
        add_relu_ln<<<T2, 128>>>(h, proj, proj2, n2_g + bo, n2_b + bo, h, 1);
        // FFN: f1 full-K, f2 split-K x2 (partials summed in add_relu_ln)
        gemm_mma<0><<<gF, 256, GSMEM>>>(h, nullptr,
            f1_w + (size_t)l * EE * FF, f1_b + (size_t)l * FF, ffn,
            f1_w + (size_t)l * EE * FF, f1_b + (size_t)l * FF, ffn,
            f1_w + (size_t)l * EE * FF, f1_b + (size_t)l * FF, ffn, FF, EE, EE, 0, 0, 1);
        gemm_mma<0><<<gP2, 256, GSMEM>>>(ffn, nullptr,
            f2_w + (size_t)l * FF * EE,                      f2_b + bo, proj,
            f2_w + (size_t)l * FF * EE + (size_t)1024 * EE,  zb,        proj2,
            f2_w + (size_t)l * FF * EE,                      f2_b + bo, proj,
            EE, FF, 1024, 1024, 0, 0);
        add_relu_ln<<<T2, 128>>>(h, proj, proj2, n3_g + bo, n3_b + bo, h, 0);
    }

    copyk<<<T2 * EE / 1024, 256>>>(h, (float*)d_out);
}